// round 6
// baseline (speedup 1.0000x reference)
#include <cuda_runtime.h>
#include <cuda_bf16.h>
#include <math.h>
#include <stdint.h>

// Problem constants
#define BB   8
#define TT   1024
#define DIN  256
#define CH   1024   // D_H1
#define OO   1024   // D_H2
#define KW   9

typedef __nv_bfloat16 bf16;

// Packed-panel format for GEMM operands:
//   operand [R][K] (K-major) -> tiles of 128 rows x 32 k,
//   byte offset = ((r>>7)*nks + (k>>5))*SEGB + (r&127)*PROWB + (k&31)*2
#define PROWB 80
#define SEGB  10240                     // 128 * 80
#define PB_X   (8 * 8 * SEGB)           // per-batch packed x   [1024][256]
#define PB_1K  (8 * 32 * SEGB)          // per-batch packed [1024][1024]
#define PB_W2  (2 * 32 * SEGB)          // packed w2 [256][1024]

__device__ __forceinline__ size_t pk_off(int r, int k, int nks) {
    return (size_t)((r >> 7) * nks + (k >> 5)) * SEGB +
           (size_t)(r & 127) * PROWB + (size_t)(k & 31) * 2;
}

// Scratch (device globals — no allocation allowed)
__device__ float g_h [BB * CH * TT];     // mish(w1(x)), [b][c][t]
__device__ float g_pwn[BB * OO];
__device__ float g_dwn[BB * KW];
__device__ __align__(128) char g_xph [BB * PB_X];
__device__ __align__(128) char g_xpl [BB * PB_X];
__device__ __align__(128) char g_w1ph[8 * 8 * SEGB];
__device__ __align__(128) char g_w1pl[8 * 8 * SEGB];
__device__ __align__(128) char g_w2ph[PB_W2];
__device__ __align__(128) char g_w2pl[PB_W2];
__device__ __align__(128) char g_pTph[BB * PB_1K];
__device__ __align__(128) char g_pTpl[BB * PB_1K];
__device__ __align__(128) char g_yTph[BB * PB_1K];
__device__ __align__(128) char g_yTpl[BB * PB_1K];
__device__ __align__(128) char g_y2ph[BB * PB_1K];
__device__ __align__(128) char g_y2pl[BB * PB_1K];

__device__ __forceinline__ float mishf(float v) {
    float sp = (v > 20.f) ? v : log1pf(__expf(v));
    return v * tanhf(sp);
}

// ---------------------------------------------------------------------------
// Norm kernels
// ---------------------------------------------------------------------------
__global__ void dwn_kernel(const float* __restrict__ d_w) {
    int b = blockIdx.x / KW, k = blockIdx.x % KW;
    __shared__ float red[256];
    float s = 0.f;
    for (int c = threadIdx.x; c < CH; c += 256) {
        float v = d_w[((long)b * CH + c) * KW + k];
        s += v * v;
    }
    red[threadIdx.x] = s;
    __syncthreads();
    for (int off = 128; off > 0; off >>= 1) {
        if (threadIdx.x < off) red[threadIdx.x] += red[threadIdx.x + off];
        __syncthreads();
    }
    if (threadIdx.x == 0)
        g_dwn[b * KW + k] = 1.f / fmaxf(sqrtf(red[0]), 1e-12f);
}

__global__ void pwn_kernel(const float* __restrict__ p_w) {
    int b  = blockIdx.x / (OO / 32);
    int o0 = (blockIdx.x % (OO / 32)) * 32;
    int oi = threadIdx.x & 31, cg = threadIdx.x >> 5;
    int o = o0 + oi;
    float s = 0.f;
    for (int c = cg; c < CH; c += 8) {
        float v = p_w[((long)b * CH + c) * OO + o];
        s += v * v;
    }
    __shared__ float red[8][33];
    red[cg][oi] = s;
    __syncthreads();
    if (cg == 0) {
        float t = 0.f;
        #pragma unroll
        for (int j = 0; j < 8; j++) t += red[j][oi];
        g_pwn[b * OO + o] = 1.f / fmaxf(sqrtf(t), 1e-12f);
    }
}

// ---------------------------------------------------------------------------
// Fused: depthwise conv + transpose + hi/lo split, packed output
// ---------------------------------------------------------------------------
__global__ void __launch_bounds__(256)
convT_kernel(const float* __restrict__ d_w, const float* __restrict__ d_g,
             const float* __restrict__ d_b, const float* __restrict__ p_g,
             char* __restrict__ hi, char* __restrict__ lo) {
    __shared__ float tile[32][41];
    int b = blockIdx.z, c0 = blockIdx.y * 32, t0 = blockIdx.x * 32;
    int tid = threadIdx.y * 32 + threadIdx.x;

    const float* hbase = g_h + ((size_t)b * CH + c0) * TT;
    #pragma unroll
    for (int i = tid; i < 32 * 40; i += 256) {
        int c = i / 40, j = i % 40;
        int t = t0 - 4 + j;
        tile[c][j] = (t >= 0 && t < TT) ? hbase[(size_t)c * TT + t] : 0.f;
    }
    __syncthreads();

    int tx = threadIdx.x;
    int c  = c0 + tx;
    float gg   = d_g[b * CH + c];
    float pg   = p_g[b * CH + c];
    float bias = d_b[b * CH + c];
    float w[KW];
    #pragma unroll
    for (int k = 0; k < KW; k++)
        w[k] = d_w[((size_t)b * CH + c) * KW + k] * g_dwn[b * KW + k] * gg;

    #pragma unroll
    for (int i = 0; i < 4; i++) {
        int tl = threadIdx.y + i * 8;
        float acc = bias;
        #pragma unroll
        for (int k = 0; k < KW; k++) acc = fmaf(tile[tx][tl + k], w[k], acc);
        float v = acc * pg;
        bf16 h = __float2bfloat16(v);
        bf16 l = __float2bfloat16(v - __bfloat162float(h));
        size_t off = (size_t)b * PB_1K + pk_off(t0 + tl, c, 32);
        *(bf16*)(hi + off) = h;
        *(bf16*)(lo + off) = l;
    }
}

// ---------------------------------------------------------------------------
// Elementwise hi/lo split to packed format. src: [batches][R][K] fp32.
// ---------------------------------------------------------------------------
__global__ void splitp_kernel(const float* __restrict__ src,
                              char* __restrict__ hi, char* __restrict__ lo,
                              int R, int K, long pb_bytes, int n4total) {
    int i = blockIdx.x * blockDim.x + threadIdx.x;
    if (i >= n4total) return;
    long e = (long)i * 4;
    long perb = (long)R * K;
    int bb = (int)(e / perb);
    long rem = e - (long)bb * perb;
    int r = (int)(rem / K), k = (int)(rem % K);
    float4 v = ((const float4*)src)[i];
    bf16 h0 = __float2bfloat16(v.x), h1 = __float2bfloat16(v.y);
    bf16 h2 = __float2bfloat16(v.z), h3 = __float2bfloat16(v.w);
    __nv_bfloat162 hA, hB, lA, lB;
    hA.x = h0; hA.y = h1; hB.x = h2; hB.y = h3;
    lA.x = __float2bfloat16(v.x - __bfloat162float(h0));
    lA.y = __float2bfloat16(v.y - __bfloat162float(h1));
    lB.x = __float2bfloat16(v.z - __bfloat162float(h2));
    lB.y = __float2bfloat16(v.w - __bfloat162float(h3));
    size_t off = (size_t)bb * pb_bytes + pk_off(r, k, K >> 5);
    uint2 hw, lw;
    hw.x = *(uint32_t*)&hA; hw.y = *(uint32_t*)&hB;
    lw.x = *(uint32_t*)&lA; lw.y = *(uint32_t*)&lB;
    *(uint2*)(hi + off) = hw;
    *(uint2*)(lo + off) = lw;
}

// ---------------------------------------------------------------------------
// Transpose + split to packed: src[b][1024][1024] -> packed rows = src cols
// ---------------------------------------------------------------------------
__global__ void tcvtp_kernel(const float* __restrict__ src,
                             char* __restrict__ hi, char* __restrict__ lo) {
    __shared__ float tile[32][33];
    int b  = blockIdx.z;
    int c0 = blockIdx.x * 32;
    int r0 = blockIdx.y * 32;
    int tx = threadIdx.x, ty = threadIdx.y;
    const float* s = src + ((size_t)b * 1024 + r0) * 1024 + c0;
    #pragma unroll
    for (int i = 0; i < 32; i += 8)
        tile[ty + i][tx] = s[(size_t)(ty + i) * 1024 + tx];
    __syncthreads();
    #pragma unroll
    for (int i = 0; i < 32; i += 8) {
        float v = tile[tx][ty + i];
        bf16 h = __float2bfloat16(v);
        bf16 l = __float2bfloat16(v - __bfloat162float(h));
        size_t off = (size_t)b * PB_1K + pk_off(c0 + ty + i, r0 + tx, 32);
        *(bf16*)(hi + off) = h;
        *(bf16*)(lo + off) = l;
    }
}

// ---------------------------------------------------------------------------
// PTX helpers
// ---------------------------------------------------------------------------
__device__ __forceinline__ uint32_t smem_u32(const void* p) {
    uint32_t a;
    asm("{ .reg .u64 t; cvta.to.shared.u64 t, %1; cvt.u32.u64 %0, t; }"
        : "=r"(a) : "l"(p));
    return a;
}

__device__ __forceinline__ void mbar_init(uint32_t m, uint32_t cnt) {
    asm volatile("mbarrier.init.shared.b64 [%0], %1;" :: "r"(m), "r"(cnt)
                 : "memory");
}

__device__ __forceinline__ void mbar_expect(uint32_t m, uint32_t tx) {
    asm volatile("mbarrier.arrive.expect_tx.shared.b64 _, [%0], %1;"
                 :: "r"(m), "r"(tx) : "memory");
}

__device__ __forceinline__ void bulk_g2s(uint32_t dst, const void* src,
                                         uint32_t bytes, uint32_t mbar) {
    asm volatile(
        "cp.async.bulk.shared::cluster.global.mbarrier::complete_tx::bytes "
        "[%0], [%1], %2, [%3];"
        :: "r"(dst), "l"(src), "r"(bytes), "r"(mbar) : "memory");
}

__device__ __forceinline__ void mbar_wait(uint32_t m, uint32_t parity) {
    uint32_t done = 0;
    while (!done)
        asm volatile(
            "{ .reg .pred P; mbarrier.try_wait.parity.shared.b64 P, [%1], %2; "
            "selp.b32 %0,1,0,P; }"
            : "=r"(done) : "r"(m), "r"(parity) : "memory");
}

__device__ __forceinline__ void ldsm4(uint32_t* r, uint32_t a) {
    asm volatile("ldmatrix.sync.aligned.m8n8.x4.shared.b16 {%0,%1,%2,%3}, [%4];"
                 : "=r"(r[0]), "=r"(r[1]), "=r"(r[2]), "=r"(r[3]) : "r"(a));
}

__device__ __forceinline__ void ldsm2(uint32_t* r, uint32_t a) {
    asm volatile("ldmatrix.sync.aligned.m8n8.x2.shared.b16 {%0,%1}, [%2];"
                 : "=r"(r[0]), "=r"(r[1]) : "r"(a));
}

__device__ __forceinline__ void mma16816(float* d, const uint32_t* a,
                                         const uint32_t* b) {
    asm volatile(
        "mma.sync.aligned.m16n8k16.row.col.f32.bf16.bf16.f32 "
        "{%0,%1,%2,%3}, {%4,%5,%6,%7}, {%8,%9}, {%0,%1,%2,%3};"
        : "+f"(d[0]), "+f"(d[1]), "+f"(d[2]), "+f"(d[3])
        : "r"(a[0]), "r"(a[1]), "r"(a[2]), "r"(a[3]), "r"(b[0]), "r"(b[1]));
}

// ---------------------------------------------------------------------------
// bf16 hi/lo split GEMM on packed-panel operands, bulk-copy loader.
// C[m][n] = sum_k A(m,k)*B(n,k); 3 MMA passes (hh + hl + lh).
// CTA tile BM x 128, BK=32, warp tile 64x32, double buffer.
//   BM=256: 512 thr, 16 warps, 1 CTA/SM (smem 120KB) — high arithmetic
//           intensity so loads fit the compute window.
//   BM=128: 256 thr, 8 warps, 2 CTAs/SM — for wave-quantization-limited GEMM3.
// EPI 1: fp32 C = mish(v + e1[m])
// EPI 2: packed bf16 hi/lo C = v*e1[b*OO+n] + e2[b*OO+n]
// EPI 3: fp32 C = v + e1[n] + e2[b][m][n]
// ---------------------------------------------------------------------------
template<int EPI, int BM>
__global__ void __launch_bounds__(BM * 2, (BM == 128) ? 2 : 1)
mma_gemm(const char* __restrict__ Ah, const char* __restrict__ Al, long sA,
         const char* __restrict__ Bh, const char* __restrict__ Bl, long sB,
         void* __restrict__ C0, void* __restrict__ C1, long sC,
         int M, int N, int K,
         const float* __restrict__ e1, const float* __restrict__ e2)
{
    constexpr int ASEG = BM * PROWB;          // A hi (or lo) bytes per stage
    constexpr int BSEG = 128 * PROWB;         // B hi (or lo) bytes per stage
    constexpr int STG  = 2 * ASEG + 2 * BSEG; // stage bytes
    constexpr int NRT  = BM / 128;            // A row-tiles per stage

    extern __shared__ __align__(128) char sm[];
    const uint32_t smb = smem_u32(sm);
    const uint32_t mb0 = smb + 2 * STG;
    const int tid = threadIdx.x, lane = tid & 31, wid = tid >> 5;
    const int b = blockIdx.z;
    const int m0 = blockIdx.y * BM, n0 = blockIdx.x * 128;
    const int wm = wid >> 2, wn = wid & 3;
    const int nk = K >> 5;

    const char* pAh = Ah + (size_t)b * sA + (size_t)(m0 >> 7) * nk * SEGB;
    const char* pAl = Al + (size_t)b * sA + (size_t)(m0 >> 7) * nk * SEGB;
    const char* pBh = Bh + (size_t)b * sB + (size_t)(n0 >> 7) * nk * SEGB;
    const char* pBl = Bl + (size_t)b * sB + (size_t)(n0 >> 7) * nk * SEGB;

    if (tid == 0) { mbar_init(mb0, 1); mbar_init(mb0 + 8, 1); }
    __syncthreads();

    float acc[4][4][4];
    #pragma unroll
    for (int i = 0; i < 4; i++)
        #pragma unroll
        for (int j = 0; j < 4; j++)
            #pragma unroll
            for (int r = 0; r < 4; r++) acc[i][j][r] = 0.f;

    auto issue = [&](int kc, int s) {
        if (tid == 0) {
            uint32_t mb = mb0 + s * 8;
            uint32_t sb = smb + s * STG;
            mbar_expect(mb, STG);
            #pragma unroll
            for (int rt = 0; rt < NRT; rt++) {
                size_t go = ((size_t)rt * nk + kc) * SEGB;
                bulk_g2s(sb + rt * SEGB,        pAh + go, SEGB, mb);
                bulk_g2s(sb + ASEG + rt * SEGB, pAl + go, SEGB, mb);
            }
            bulk_g2s(sb + 2 * ASEG,        pBh + (size_t)kc * SEGB, SEGB, mb);
            bulk_g2s(sb + 2 * ASEG + BSEG, pBl + (size_t)kc * SEGB, SEGB, mb);
        }
    };

    // Per-warp A row-tile is constant (64-row warp tiles never straddle 128)
    const uint32_t a_tile_off = (uint32_t)((wm >> 1) * SEGB);
    const int a_row_in_tile = (wm & 1) * 64;

    auto compute = [&](int s) {
        const uint32_t sb = smb + s * STG;
        #pragma unroll
        for (int ks = 0; ks < 2; ks++) {
            uint32_t ah[4][4], al[4][4], bh[4][2], bl[4][2];
            #pragma unroll
            for (int i = 0; i < 4; i++) {
                uint32_t ad = sb + a_tile_off +
                    (uint32_t)((a_row_in_tile + i * 16 + (lane & 15)) * PROWB) +
                    ks * 32 + (lane >> 4) * 16;
                ldsm4(ah[i], ad);
                ldsm4(al[i], ad + ASEG);
            }
            #pragma unroll
            for (int j = 0; j < 4; j++) {
                uint32_t bd = sb + 2 * ASEG +
                    (uint32_t)((wn * 32 + j * 8 + (lane & 7)) * PROWB) +
                    ks * 32 + ((lane >> 3) & 1) * 16;
                ldsm2(bh[j], bd);
                ldsm2(bl[j], bd + BSEG);
            }
            #pragma unroll
            for (int i = 0; i < 4; i++)
                #pragma unroll
                for (int j = 0; j < 4; j++) {
                    mma16816(acc[i][j], ah[i], bh[j]);
                    mma16816(acc[i][j], ah[i], bl[j]);
                    mma16816(acc[i][j], al[i], bh[j]);
                }
        }
    };

    issue(0, 0);
    if (nk > 1) issue(1, 1);
    for (int kc = 0; kc < nk; kc++) {
        int s = kc & 1;
        mbar_wait(mb0 + s * 8, (kc >> 1) & 1);
        compute(s);
        __syncthreads();
        if (kc + 2 < nk) issue(kc + 2, s);
    }

    // --- epilogue ---
    const float* E1 = e1;
    const float* E2 = e2;
    if (EPI == 2) { E1 = e1 + b * OO; E2 = e2 + b * OO; }
    if (EPI == 3) { E2 = e2 + (size_t)b * M * N; }

    char* C0b = (char*)C0 + (size_t)b * sC;
    char* C1b = (char*)C1 + (EPI == 2 ? (size_t)b * sC : 0);

    const int mrow0 = m0 + wm * 64;
    const int ncol0 = n0 + wn * 32;
    #pragma unroll
    for (int i = 0; i < 4; i++) {
        #pragma unroll
        for (int r = 0; r < 2; r++) {
            int m = mrow0 + i * 16 + (lane >> 2) + r * 8;
            #pragma unroll
            for (int j = 0; j < 4; j++) {
                int n = ncol0 + j * 8 + (lane & 3) * 2;
                float v0 = acc[i][j][r * 2 + 0];
                float v1 = acc[i][j][r * 2 + 1];
                size_t off = (size_t)m * N + n;
                if (EPI == 1) {
                    float bb = E1[m];
                    float2 o; o.x = mishf(v0 + bb); o.y = mishf(v1 + bb);
                    *(float2*)((float*)C0b + off) = o;
                } else if (EPI == 2) {
                    v0 = v0 * E1[n] + E2[n];
                    v1 = v1 * E1[n + 1] + E2[n + 1];
                    __nv_bfloat162 hv, lv;
                    hv.x = __float2bfloat16(v0);
                    hv.y = __float2bfloat16(v1);
                    lv.x = __float2bfloat16(v0 - __bfloat162float(hv.x));
                    lv.y = __float2bfloat16(v1 - __bfloat162float(hv.y));
                    size_t po = pk_off(m, n, N >> 5);
                    *(uint32_t*)(C0b + po) = *(uint32_t*)&hv;
                    *(uint32_t*)(C1b + po) = *(uint32_t*)&lv;
                } else {
                    float2 o;
                    o.x = v0 + E1[n]     + E2[off];
                    o.y = v1 + E1[n + 1] + E2[off + 1];
                    *(float2*)((float*)C0b + off) = o;
                }
            }
        }
    }
}

#define SMEM_OF(BM_) (2 * (2 * (BM_) * PROWB + 2 * 128 * PROWB) + 16)

// ---------------------------------------------------------------------------
extern "C" void kernel_launch(void* const* d_in, const int* in_sizes, int n_in,
                              void* d_out, int out_size) {
    const float* x    = (const float*)d_in[0];
    const float* d_w  = (const float*)d_in[1];
    const float* d_g  = (const float*)d_in[2];
    const float* d_b  = (const float*)d_in[3];
    const float* p_w  = (const float*)d_in[4];
    const float* p_g  = (const float*)d_in[5];
    const float* p_b  = (const float*)d_in[6];
    const float* w1_w = (const float*)d_in[7];
    const float* w1_b = (const float*)d_in[8];
    const float* w2_w = (const float*)d_in[9];
    const float* w2_b = (const float*)d_in[10];
    float* out = (float*)d_out;

    void *p_gh, *p_gpwn;
    void *p_xh, *p_xl, *p_w1h, *p_w1l, *p_w2h, *p_w2l;
    void *p_pth, *p_ptl, *p_yth, *p_ytl, *p_y2h, *p_y2l;
    cudaGetSymbolAddress(&p_gh,   g_h);
    cudaGetSymbolAddress(&p_gpwn, g_pwn);
    cudaGetSymbolAddress(&p_xh,   g_xph);
    cudaGetSymbolAddress(&p_xl,   g_xpl);
    cudaGetSymbolAddress(&p_w1h,  g_w1ph);
    cudaGetSymbolAddress(&p_w1l,  g_w1pl);
    cudaGetSymbolAddress(&p_w2h,  g_w2ph);
    cudaGetSymbolAddress(&p_w2l,  g_w2pl);
    cudaGetSymbolAddress(&p_pth,  g_pTph);
    cudaGetSymbolAddress(&p_ptl,  g_pTpl);
    cudaGetSymbolAddress(&p_yth,  g_yTph);
    cudaGetSymbolAddress(&p_ytl,  g_yTpl);
    cudaGetSymbolAddress(&p_y2h,  g_y2ph);
    cudaGetSymbolAddress(&p_y2l,  g_y2pl);
    float* gh   = (float*)p_gh;
    float* gpwn = (float*)p_gpwn;

    cudaFuncSetAttribute(mma_gemm<1, 256>,
                         cudaFuncAttributeMaxDynamicSharedMemorySize,
                         SMEM_OF(256));
    cudaFuncSetAttribute(mma_gemm<2, 256>,
                         cudaFuncAttributeMaxDynamicSharedMemorySize,
                         SMEM_OF(256));
    cudaFuncSetAttribute(mma_gemm<3, 128>,
                         cudaFuncAttributeMaxDynamicSharedMemorySize,
                         SMEM_OF(128));

    // 1) norms + packed input conversions
    dwn_kernel<<<BB * KW, 256>>>(d_w);
    pwn_kernel<<<BB * (OO / 32), 256>>>(p_w);
    splitp_kernel<<<(BB * TT * DIN / 4 + 255) / 256, 256>>>(
        x, (char*)p_xh, (char*)p_xl, TT, DIN, PB_X, BB * TT * DIN / 4);
    splitp_kernel<<<(CH * DIN / 4 + 255) / 256, 256>>>(
        w1_w, (char*)p_w1h, (char*)p_w1l, CH, DIN, 0L, CH * DIN / 4);
    splitp_kernel<<<(DIN * OO / 4 + 255) / 256, 256>>>(
        w2_w, (char*)p_w2h, (char*)p_w2l, DIN, OO, 0L, DIN * OO / 4);
    {
        dim3 grid(32, 32, BB);
        tcvtp_kernel<<<grid, dim3(32, 8)>>>(p_w, (char*)p_pth, (char*)p_ptl);
    }

    // 2) GEMM1: h = mish(w1 . x + w1_b)   M=CH, N=TT, K=DIN
    {
        dim3 grid(TT / 128, CH / 256, BB);
        mma_gemm<1, 256><<<grid, 512, SMEM_OF(256)>>>(
            (char*)p_w1h, (char*)p_w1l, 0L,
            (char*)p_xh,  (char*)p_xl,  (long)PB_X,
            gh, nullptr, (long)CH * TT * 4,
            CH, TT, DIN, w1_b, nullptr);
    }

    // 3) fused conv + transpose + split -> yT packed
    {
        dim3 grid(TT / 32, CH / 32, BB);
        convT_kernel<<<grid, dim3(32, 8)>>>(d_w, d_g, d_b, p_g,
                                            (char*)p_yth, (char*)p_ytl);
    }

    // 4) GEMM2: y2 = (yT . pT)*pwn + p_b   M=TT, N=OO, K=CH  (packed out)
    {
        dim3 grid(OO / 128, TT / 256, BB);
        mma_gemm<2, 256><<<grid, 512, SMEM_OF(256)>>>(
            (char*)p_yth, (char*)p_ytl, (long)PB_1K,
            (char*)p_pth, (char*)p_ptl, (long)PB_1K,
            p_y2h, p_y2l, (long)PB_1K,
            TT, OO, CH, gpwn, p_b);
    }

    // 5) GEMM3: out = y2 . w2^T + w2_b + x   M=TT, N=DIN, K=OO
    {
        dim3 grid(DIN / 128, TT / 128, BB);
        mma_gemm<3, 128><<<grid, 256, SMEM_OF(128)>>>(
            (char*)p_y2h, (char*)p_y2l, (long)PB_1K,
            (char*)p_w2h, (char*)p_w2l, 0L,
            out, nullptr, (long)TT * DIN * 4,
            TT, DIN, OO, w2_b, x);
    }
}

// round 7
// speedup vs baseline: 1.0596x; 1.0596x over previous
#include <cuda_runtime.h>
#include <cuda_bf16.h>
#include <math.h>
#include <stdint.h>

// Problem constants
#define BB   8
#define TT   1024
#define DIN  256
#define CH   1024   // D_H1
#define OO   1024   // D_H2
#define KW   9

typedef __nv_bfloat16 bf16;

// Packed-panel format for GEMM operands:
//   operand [R][K] (K-major) -> tiles of 128 rows x 32 k,
//   byte offset = ((r>>7)*nks + (k>>5))*SEGB + (r&127)*PROWB + (k&31)*2
#define PROWB 80
#define SEGB  10240                     // 128 * 80
#define PB_X   (8 * 8 * SEGB)           // per-batch packed x   [1024][256]
#define PB_1K  (8 * 32 * SEGB)          // per-batch packed [1024][1024]
#define PB_W2  (2 * 32 * SEGB)          // packed w2 [256][1024]

__device__ __forceinline__ size_t pk_off(int r, int k, int nks) {
    return (size_t)((r >> 7) * nks + (k >> 5)) * SEGB +
           (size_t)(r & 127) * PROWB + (size_t)(k & 31) * 2;
}

// Scratch (device globals — no allocation allowed)
__device__ float g_h [BB * CH * TT];     // mish(w1(x)), [b][c][t]
__device__ float g_pwn[BB * OO];
__device__ float g_dwn[BB * KW];
__device__ __align__(128) char g_xph [BB * PB_X];
__device__ __align__(128) char g_xpl [BB * PB_X];
__device__ __align__(128) char g_w1ph[8 * 8 * SEGB];
__device__ __align__(128) char g_w1pl[8 * 8 * SEGB];
__device__ __align__(128) char g_w2ph[PB_W2];
__device__ __align__(128) char g_w2pl[PB_W2];
__device__ __align__(128) char g_pTph[BB * PB_1K];
__device__ __align__(128) char g_pTpl[BB * PB_1K];
__device__ __align__(128) char g_yTph[BB * PB_1K];
__device__ __align__(128) char g_yTpl[BB * PB_1K];
__device__ __align__(128) char g_y2ph[BB * PB_1K];
__device__ __align__(128) char g_y2pl[BB * PB_1K];

__device__ __forceinline__ float mishf(float v) {
    float sp = (v > 20.f) ? v : log1pf(__expf(v));
    return v * tanhf(sp);
}

// ---------------------------------------------------------------------------
// Norm kernels
// ---------------------------------------------------------------------------
__global__ void dwn_kernel(const float* __restrict__ d_w) {
    int b = blockIdx.x / KW, k = blockIdx.x % KW;
    __shared__ float red[256];
    float s = 0.f;
    for (int c = threadIdx.x; c < CH; c += 256) {
        float v = d_w[((long)b * CH + c) * KW + k];
        s += v * v;
    }
    red[threadIdx.x] = s;
    __syncthreads();
    for (int off = 128; off > 0; off >>= 1) {
        if (threadIdx.x < off) red[threadIdx.x] += red[threadIdx.x + off];
        __syncthreads();
    }
    if (threadIdx.x == 0)
        g_dwn[b * KW + k] = 1.f / fmaxf(sqrtf(red[0]), 1e-12f);
}

__global__ void pwn_kernel(const float* __restrict__ p_w) {
    int b  = blockIdx.x / (OO / 32);
    int o0 = (blockIdx.x % (OO / 32)) * 32;
    int oi = threadIdx.x & 31, cg = threadIdx.x >> 5;
    int o = o0 + oi;
    float s = 0.f;
    for (int c = cg; c < CH; c += 8) {
        float v = p_w[((long)b * CH + c) * OO + o];
        s += v * v;
    }
    __shared__ float red[8][33];
    red[cg][oi] = s;
    __syncthreads();
    if (cg == 0) {
        float t = 0.f;
        #pragma unroll
        for (int j = 0; j < 8; j++) t += red[j][oi];
        g_pwn[b * OO + o] = 1.f / fmaxf(sqrtf(t), 1e-12f);
    }
}

// ---------------------------------------------------------------------------
// Fused: depthwise conv + transpose + hi/lo split, packed output
// ---------------------------------------------------------------------------
__global__ void __launch_bounds__(256)
convT_kernel(const float* __restrict__ d_w, const float* __restrict__ d_g,
             const float* __restrict__ d_b, const float* __restrict__ p_g,
             char* __restrict__ hi, char* __restrict__ lo) {
    __shared__ float tile[32][41];
    int b = blockIdx.z, c0 = blockIdx.y * 32, t0 = blockIdx.x * 32;
    int tid = threadIdx.y * 32 + threadIdx.x;

    const float* hbase = g_h + ((size_t)b * CH + c0) * TT;
    #pragma unroll
    for (int i = tid; i < 32 * 40; i += 256) {
        int c = i / 40, j = i % 40;
        int t = t0 - 4 + j;
        tile[c][j] = (t >= 0 && t < TT) ? hbase[(size_t)c * TT + t] : 0.f;
    }
    __syncthreads();

    int tx = threadIdx.x;
    int c  = c0 + tx;
    float gg   = d_g[b * CH + c];
    float pg   = p_g[b * CH + c];
    float bias = d_b[b * CH + c];
    float w[KW];
    #pragma unroll
    for (int k = 0; k < KW; k++)
        w[k] = d_w[((size_t)b * CH + c) * KW + k] * g_dwn[b * KW + k] * gg;

    #pragma unroll
    for (int i = 0; i < 4; i++) {
        int tl = threadIdx.y + i * 8;
        float acc = bias;
        #pragma unroll
        for (int k = 0; k < KW; k++) acc = fmaf(tile[tx][tl + k], w[k], acc);
        float v = acc * pg;
        bf16 h = __float2bfloat16(v);
        bf16 l = __float2bfloat16(v - __bfloat162float(h));
        size_t off = (size_t)b * PB_1K + pk_off(t0 + tl, c, 32);
        *(bf16*)(hi + off) = h;
        *(bf16*)(lo + off) = l;
    }
}

// ---------------------------------------------------------------------------
// Elementwise hi/lo split to packed format. src: [batches][R][K] fp32.
// ---------------------------------------------------------------------------
__global__ void splitp_kernel(const float* __restrict__ src,
                              char* __restrict__ hi, char* __restrict__ lo,
                              int R, int K, long pb_bytes, int n4total) {
    int i = blockIdx.x * blockDim.x + threadIdx.x;
    if (i >= n4total) return;
    long e = (long)i * 4;
    long perb = (long)R * K;
    int bb = (int)(e / perb);
    long rem = e - (long)bb * perb;
    int r = (int)(rem / K), k = (int)(rem % K);
    float4 v = ((const float4*)src)[i];
    bf16 h0 = __float2bfloat16(v.x), h1 = __float2bfloat16(v.y);
    bf16 h2 = __float2bfloat16(v.z), h3 = __float2bfloat16(v.w);
    __nv_bfloat162 hA, hB, lA, lB;
    hA.x = h0; hA.y = h1; hB.x = h2; hB.y = h3;
    lA.x = __float2bfloat16(v.x - __bfloat162float(h0));
    lA.y = __float2bfloat16(v.y - __bfloat162float(h1));
    lB.x = __float2bfloat16(v.z - __bfloat162float(h2));
    lB.y = __float2bfloat16(v.w - __bfloat162float(h3));
    size_t off = (size_t)bb * pb_bytes + pk_off(r, k, K >> 5);
    uint2 hw, lw;
    hw.x = *(uint32_t*)&hA; hw.y = *(uint32_t*)&hB;
    lw.x = *(uint32_t*)&lA; lw.y = *(uint32_t*)&lB;
    *(uint2*)(hi + off) = hw;
    *(uint2*)(lo + off) = lw;
}

// ---------------------------------------------------------------------------
// Transpose + split to packed: src[b][1024][1024] -> packed rows = src cols
// ---------------------------------------------------------------------------
__global__ void tcvtp_kernel(const float* __restrict__ src,
                             char* __restrict__ hi, char* __restrict__ lo) {
    __shared__ float tile[32][33];
    int b  = blockIdx.z;
    int c0 = blockIdx.x * 32;
    int r0 = blockIdx.y * 32;
    int tx = threadIdx.x, ty = threadIdx.y;
    const float* s = src + ((size_t)b * 1024 + r0) * 1024 + c0;
    #pragma unroll
    for (int i = 0; i < 32; i += 8)
        tile[ty + i][tx] = s[(size_t)(ty + i) * 1024 + tx];
    __syncthreads();
    #pragma unroll
    for (int i = 0; i < 32; i += 8) {
        float v = tile[tx][ty + i];
        bf16 h = __float2bfloat16(v);
        bf16 l = __float2bfloat16(v - __bfloat162float(h));
        size_t off = (size_t)b * PB_1K + pk_off(c0 + ty + i, r0 + tx, 32);
        *(bf16*)(hi + off) = h;
        *(bf16*)(lo + off) = l;
    }
}

// ---------------------------------------------------------------------------
// PTX helpers
// ---------------------------------------------------------------------------
__device__ __forceinline__ uint32_t smem_u32(const void* p) {
    uint32_t a;
    asm("{ .reg .u64 t; cvta.to.shared.u64 t, %1; cvt.u32.u64 %0, t; }"
        : "=r"(a) : "l"(p));
    return a;
}

__device__ __forceinline__ void mbar_init(uint32_t m, uint32_t cnt) {
    asm volatile("mbarrier.init.shared.b64 [%0], %1;" :: "r"(m), "r"(cnt)
                 : "memory");
}

__device__ __forceinline__ void mbar_expect(uint32_t m, uint32_t tx) {
    asm volatile("mbarrier.arrive.expect_tx.shared.b64 _, [%0], %1;"
                 :: "r"(m), "r"(tx) : "memory");
}

__device__ __forceinline__ void bulk_g2s(uint32_t dst, const void* src,
                                         uint32_t bytes, uint32_t mbar) {
    asm volatile(
        "cp.async.bulk.shared::cluster.global.mbarrier::complete_tx::bytes "
        "[%0], [%1], %2, [%3];"
        :: "r"(dst), "l"(src), "r"(bytes), "r"(mbar) : "memory");
}

__device__ __forceinline__ void mbar_wait(uint32_t m, uint32_t parity) {
    uint32_t done = 0;
    while (!done)
        asm volatile(
            "{ .reg .pred P; mbarrier.try_wait.parity.shared.b64 P, [%1], %2; "
            "selp.b32 %0,1,0,P; }"
            : "=r"(done) : "r"(m), "r"(parity) : "memory");
}

__device__ __forceinline__ void ldsm4(uint32_t* r, uint32_t a) {
    asm volatile("ldmatrix.sync.aligned.m8n8.x4.shared.b16 {%0,%1,%2,%3}, [%4];"
                 : "=r"(r[0]), "=r"(r[1]), "=r"(r[2]), "=r"(r[3]) : "r"(a));
}

__device__ __forceinline__ void ldsm2(uint32_t* r, uint32_t a) {
    asm volatile("ldmatrix.sync.aligned.m8n8.x2.shared.b16 {%0,%1}, [%2];"
                 : "=r"(r[0]), "=r"(r[1]) : "r"(a));
}

__device__ __forceinline__ void mma16816(float* d, const uint32_t* a,
                                         const uint32_t* b) {
    asm volatile(
        "mma.sync.aligned.m16n8k16.row.col.f32.bf16.bf16.f32 "
        "{%0,%1,%2,%3}, {%4,%5,%6,%7}, {%8,%9}, {%0,%1,%2,%3};"
        : "+f"(d[0]), "+f"(d[1]), "+f"(d[2]), "+f"(d[3])
        : "r"(a[0]), "r"(a[1]), "r"(a[2]), "r"(a[3]), "r"(b[0]), "r"(b[1]));
}

// ---------------------------------------------------------------------------
// bf16 hi/lo split GEMM on packed-panel operands, bulk-copy loader.
// C[m][n] = sum_k A(m,k)*B(n,k); 3 MMA passes (hh + hl + lh).
// CTA 128x128, BK=32, 8 warps, warp tile 64x32, double buffer, 2 CTAs/SM.
// Split-barrier pipeline: mb_hi gates {Ah,Bh,Bl} -> hh+hl passes (phase 1);
// mb_lo gates {Al} -> lh pass (phase 2). Compute starts at 75% arrival and
// Al has all of phase 1 to land.
// EPI 1: fp32 C = mish(v + e1[m])
// EPI 2: packed bf16 hi/lo C = v*e1[b*OO+n] + e2[b*OO+n]
// EPI 3: fp32 C = v + e1[n] + e2[b][m][n]
// ---------------------------------------------------------------------------
#define SEG  SEGB                        // 10240 B per operand segment
#define STG  (4 * SEG)
#define SMEM_MMA (2 * STG + 32)          // + 4 mbarriers

template<int EPI>
__global__ void __launch_bounds__(256, 2)
mma_gemm(const char* __restrict__ Ah, const char* __restrict__ Al, long sA,
         const char* __restrict__ Bh, const char* __restrict__ Bl, long sB,
         void* __restrict__ C0, void* __restrict__ C1, long sC,
         int M, int N, int K,
         const float* __restrict__ e1, const float* __restrict__ e2)
{
    extern __shared__ __align__(128) char sm[];
    const uint32_t smb = smem_u32(sm);
    const uint32_t mb0 = smb + 2 * STG;     // [hi0, lo0, hi1, lo1] x 8B
    const int tid = threadIdx.x, lane = tid & 31, wid = tid >> 5;
    const int b = blockIdx.z;
    const int m0 = blockIdx.y * 128, n0 = blockIdx.x * 128;
    const int wm = wid >> 2, wn = wid & 3;
    const int nk = K >> 5;

    const char* pAh = Ah + (size_t)b * sA + (size_t)(m0 >> 7) * nk * SEGB;
    const char* pAl = Al + (size_t)b * sA + (size_t)(m0 >> 7) * nk * SEGB;
    const char* pBh = Bh + (size_t)b * sB + (size_t)(n0 >> 7) * nk * SEGB;
    const char* pBl = Bl + (size_t)b * sB + (size_t)(n0 >> 7) * nk * SEGB;

    if (tid == 0) {
        mbar_init(mb0 +  0, 1); mbar_init(mb0 +  8, 1);
        mbar_init(mb0 + 16, 1); mbar_init(mb0 + 24, 1);
    }
    __syncthreads();

    float acc[4][4][4];
    #pragma unroll
    for (int i = 0; i < 4; i++)
        #pragma unroll
        for (int j = 0; j < 4; j++)
            #pragma unroll
            for (int r = 0; r < 4; r++) acc[i][j][r] = 0.f;

    auto issue = [&](int kc, int s) {
        if (tid == 0) {
            uint32_t mh = mb0 + s * 16, ml = mh + 8;
            uint32_t sb = smb + s * STG;
            size_t go = (size_t)kc * SEGB;
            mbar_expect(mh, 3 * SEG);
            bulk_g2s(sb + 0 * SEG, pAh + go, SEG, mh);
            bulk_g2s(sb + 2 * SEG, pBh + go, SEG, mh);
            bulk_g2s(sb + 3 * SEG, pBl + go, SEG, mh);
            mbar_expect(ml, SEG);
            bulk_g2s(sb + 1 * SEG, pAl + go, SEG, ml);
        }
    };

    // Phase 1: hh + hl (needs Ah, Bh, Bl)
    auto compute_hi = [&](int s) {
        const uint32_t sb = smb + s * STG;
        #pragma unroll
        for (int ks = 0; ks < 2; ks++) {
            uint32_t ah[4][4], bh[4][2], bl[4][2];
            #pragma unroll
            for (int i = 0; i < 4; i++) {
                uint32_t ad = sb +
                    (uint32_t)((wm * 64 + i * 16 + (lane & 15)) * PROWB) +
                    ks * 32 + (lane >> 4) * 16;
                ldsm4(ah[i], ad);
            }
            #pragma unroll
            for (int j = 0; j < 4; j++) {
                uint32_t bd = sb + 2 * SEG +
                    (uint32_t)((wn * 32 + j * 8 + (lane & 7)) * PROWB) +
                    ks * 32 + ((lane >> 3) & 1) * 16;
                ldsm2(bh[j], bd);
                ldsm2(bl[j], bd + SEG);
            }
            #pragma unroll
            for (int i = 0; i < 4; i++)
                #pragma unroll
                for (int j = 0; j < 4; j++) {
                    mma16816(acc[i][j], ah[i], bh[j]);
                    mma16816(acc[i][j], ah[i], bl[j]);
                }
        }
    };

    // Phase 2: lh (needs Al, Bh)
    auto compute_lo = [&](int s) {
        const uint32_t sb = smb + s * STG;
        #pragma unroll
        for (int ks = 0; ks < 2; ks++) {
            uint32_t al[4][4], bh[4][2];
            #pragma unroll
            for (int i = 0; i < 4; i++) {
                uint32_t ad = sb + SEG +
                    (uint32_t)((wm * 64 + i * 16 + (lane & 15)) * PROWB) +
                    ks * 32 + (lane >> 4) * 16;
                ldsm4(al[i], ad);
            }
            #pragma unroll
            for (int j = 0; j < 4; j++) {
                uint32_t bd = sb + 2 * SEG +
                    (uint32_t)((wn * 32 + j * 8 + (lane & 7)) * PROWB) +
                    ks * 32 + ((lane >> 3) & 1) * 16;
                ldsm2(bh[j], bd);
            }
            #pragma unroll
            for (int i = 0; i < 4; i++)
                #pragma unroll
                for (int j = 0; j < 4; j++)
                    mma16816(acc[i][j], al[i], bh[j]);
        }
    };

    issue(0, 0);
    if (nk > 1) issue(1, 1);
    for (int kc = 0; kc < nk; kc++) {
        int s = kc & 1;
        uint32_t par = (kc >> 1) & 1;
        mbar_wait(mb0 + s * 16, par);        // hi: Ah, Bh, Bl
        compute_hi(s);
        mbar_wait(mb0 + s * 16 + 8, par);    // lo: Al
        compute_lo(s);
        __syncthreads();
        if (kc + 2 < nk) issue(kc + 2, s);
    }

    // --- epilogue ---
    const float* E1 = e1;
    const float* E2 = e2;
    if (EPI == 2) { E1 = e1 + b * OO; E2 = e2 + b * OO; }
    if (EPI == 3) { E2 = e2 + (size_t)b * M * N; }

    char* C0b = (char*)C0 + (size_t)b * sC;
    char* C1b = (char*)C1 + (EPI == 2 ? (size_t)b * sC : 0);

    const int mrow0 = m0 + wm * 64;
    const int ncol0 = n0 + wn * 32;
    #pragma unroll
    for (int i = 0; i < 4; i++) {
        #pragma unroll
        for (int r = 0; r < 2; r++) {
            int m = mrow0 + i * 16 + (lane >> 2) + r * 8;
            #pragma unroll
            for (int j = 0; j < 4; j++) {
                int n = ncol0 + j * 8 + (lane & 3) * 2;
                float v0 = acc[i][j][r * 2 + 0];
                float v1 = acc[i][j][r * 2 + 1];
                size_t off = (size_t)m * N + n;
                if (EPI == 1) {
                    float bb = E1[m];
                    float2 o; o.x = mishf(v0 + bb); o.y = mishf(v1 + bb);
                    *(float2*)((float*)C0b + off) = o;
                } else if (EPI == 2) {
                    v0 = v0 * E1[n] + E2[n];
                    v1 = v1 * E1[n + 1] + E2[n + 1];
                    __nv_bfloat162 hv, lv;
                    hv.x = __float2bfloat16(v0);
                    hv.y = __float2bfloat16(v1);
                    lv.x = __float2bfloat16(v0 - __bfloat162float(hv.x));
                    lv.y = __float2bfloat16(v1 - __bfloat162float(hv.y));
                    size_t po = pk_off(m, n, N >> 5);
                    *(uint32_t*)(C0b + po) = *(uint32_t*)&hv;
                    *(uint32_t*)(C1b + po) = *(uint32_t*)&lv;
                } else {
                    float2 o;
                    o.x = v0 + E1[n]     + E2[off];
                    o.y = v1 + E1[n + 1] + E2[off + 1];
                    *(float2*)((float*)C0b + off) = o;
                }
            }
        }
    }
}

// ---------------------------------------------------------------------------
extern "C" void kernel_launch(void* const* d_in, const int* in_sizes, int n_in,
                              void* d_out, int out_size) {
    const float* x    = (const float*)d_in[0];
    const float* d_w  = (const float*)d_in[1];
    const float* d_g  = (const float*)d_in[2];
    const float* d_b  = (const float*)d_in[3];
    const float* p_w  = (const float*)d_in[4];
    const float* p_g  = (const float*)d_in[5];
    const float* p_b  = (const float*)d_in[6];
    const float* w1_w = (const float*)d_in[7];
    const float* w1_b = (const float*)d_in[8];
    const float* w2_w = (const float*)d_in[9];
    const float* w2_b = (const float*)d_in[10];
    float* out = (float*)d_out;

    void *p_gh, *p_gpwn;
    void *p_xh, *p_xl, *p_w1h, *p_w1l, *p_w2h, *p_w2l;
    void *p_pth, *p_ptl, *p_yth, *p_ytl, *p_y2h, *p_y2l;
    cudaGetSymbolAddress(&p_gh,   g_h);
    cudaGetSymbolAddress(&p_gpwn, g_pwn);
    cudaGetSymbolAddress(&p_xh,   g_xph);
    cudaGetSymbolAddress(&p_xl,   g_xpl);
    cudaGetSymbolAddress(&p_w1h,  g_w1ph);
    cudaGetSymbolAddress(&p_w1l,  g_w1pl);
    cudaGetSymbolAddress(&p_w2h,  g_w2ph);
    cudaGetSymbolAddress(&p_w2l,  g_w2pl);
    cudaGetSymbolAddress(&p_pth,  g_pTph);
    cudaGetSymbolAddress(&p_ptl,  g_pTpl);
    cudaGetSymbolAddress(&p_yth,  g_yTph);
    cudaGetSymbolAddress(&p_ytl,  g_yTpl);
    cudaGetSymbolAddress(&p_y2h,  g_y2ph);
    cudaGetSymbolAddress(&p_y2l,  g_y2pl);
    float* gh   = (float*)p_gh;
    float* gpwn = (float*)p_gpwn;

    cudaFuncSetAttribute(mma_gemm<1>,
                         cudaFuncAttributeMaxDynamicSharedMemorySize, SMEM_MMA);
    cudaFuncSetAttribute(mma_gemm<2>,
                         cudaFuncAttributeMaxDynamicSharedMemorySize, SMEM_MMA);
    cudaFuncSetAttribute(mma_gemm<3>,
                         cudaFuncAttributeMaxDynamicSharedMemorySize, SMEM_MMA);

    // 1) norms + packed input conversions
    dwn_kernel<<<BB * KW, 256>>>(d_w);
    pwn_kernel<<<BB * (OO / 32), 256>>>(p_w);
    splitp_kernel<<<(BB * TT * DIN / 4 + 255) / 256, 256>>>(
        x, (char*)p_xh, (char*)p_xl, TT, DIN, PB_X, BB * TT * DIN / 4);
    splitp_kernel<<<(CH * DIN / 4 + 255) / 256, 256>>>(
        w1_w, (char*)p_w1h, (char*)p_w1l, CH, DIN, 0L, CH * DIN / 4);
    splitp_kernel<<<(DIN * OO / 4 + 255) / 256, 256>>>(
        w2_w, (char*)p_w2h, (char*)p_w2l, DIN, OO, 0L, DIN * OO / 4);
    {
        dim3 grid(32, 32, BB);
        tcvtp_kernel<<<grid, dim3(32, 8)>>>(p_w, (char*)p_pth, (char*)p_ptl);
    }

    // 2) GEMM1: h = mish(w1 . x + w1_b)   M=CH, N=TT, K=DIN
    {
        dim3 grid(TT / 128, CH / 128, BB);
        mma_gemm<1><<<grid, 256, SMEM_MMA>>>(
            (char*)p_w1h, (char*)p_w1l, 0L,
            (char*)p_xh,  (char*)p_xl,  (long)PB_X,
            gh, nullptr, (long)CH * TT * 4,
            CH, TT, DIN, w1_b, nullptr);
    }

    // 3) fused conv + transpose + split -> yT packed
    {
        dim3 grid(TT / 32, CH / 32, BB);
        convT_kernel<<<grid, dim3(32, 8)>>>(d_w, d_g, d_b, p_g,
                                            (char*)p_yth, (char*)p_ytl);
    }

    // 4) GEMM2: y2 = (yT . pT)*pwn + p_b   M=TT, N=OO, K=CH  (packed out)
    {
        dim3 grid(OO / 128, TT / 128, BB);
        mma_gemm<2><<<grid, 256, SMEM_MMA>>>(
            (char*)p_yth, (char*)p_ytl, (long)PB_1K,
            (char*)p_pth, (char*)p_ptl, (long)PB_1K,
            p_y2h, p_y2l, (long)PB_1K,
            TT, OO, CH, gpwn, p_b);
    }

    // 5) GEMM3: out = y2 . w2^T + w2_b + x   M=TT, N=DIN, K=OO
    {
        dim3 grid(DIN / 128, TT / 128, BB);
        mma_gemm<3><<<grid, 256, SMEM_MMA>>>(
            (char*)p_y2h, (char*)p_y2l, (long)PB_1K,
            (char*)p_w2h, (char*)p_w2l, 0L,
            out, nullptr, (long)TT * DIN * 4,
            TT, DIN, OO, w2_b, x);
    }
}

// round 8
// speedup vs baseline: 1.3332x; 1.2582x over previous
#include <cuda_runtime.h>
#include <cuda_fp16.h>
#include <math.h>
#include <stdint.h>

// Problem constants
#define BB   8
#define TT   1024
#define DIN  256
#define CH   1024   // D_H1
#define OO   1024   // D_H2
#define KW   9

// Packed-panel format for GEMM operands (fp16, 2 bytes):
//   operand [R][K] (K-major) -> tiles of 128 rows x 32 k,
//   byte offset = ((r>>7)*nks + (k>>5))*SEGB + (r&127)*PROWB + (k&31)*2
#define PROWB 80
#define SEGB  10240                     // 128 * 80
#define PB_X   (8 * 8 * SEGB)           // per-batch packed x   [1024][256]
#define PB_1K  (8 * 32 * SEGB)          // per-batch packed [1024][1024]
#define PB_W2  (2 * 32 * SEGB)          // packed w2 [256][1024]

__device__ __forceinline__ size_t pk_off(int r, int k, int nks) {
    return (size_t)((r >> 7) * nks + (k >> 5)) * SEGB +
           (size_t)(r & 127) * PROWB + (size_t)(k & 31) * 2;
}

// Scratch (device globals — no allocation allowed)
__device__ float g_h [BB * CH * TT];     // mish(w1(x)), [b][c][t]
__device__ float g_pwn[BB * OO];
__device__ float g_dwn[BB * KW];
// A operands: hi only (2-pass split quantizes A to fp16).
// B operands: hi + lo (B accurate to ~22 bits).
__device__ __align__(128) char g_xph [BB * PB_X];   // B of GEMM1
__device__ __align__(128) char g_xpl [BB * PB_X];
__device__ __align__(128) char g_w1ph[8 * 8 * SEGB]; // A of GEMM1 (hi only)
__device__ __align__(128) char g_w2ph[PB_W2];        // B of GEMM3
__device__ __align__(128) char g_w2pl[PB_W2];
__device__ __align__(128) char g_pTph[BB * PB_1K];   // B of GEMM2
__device__ __align__(128) char g_pTpl[BB * PB_1K];
__device__ __align__(128) char g_yTph[BB * PB_1K];   // A of GEMM2 (hi only)
__device__ __align__(128) char g_y2ph[BB * PB_1K];   // A of GEMM3 (hi only)

__device__ __forceinline__ float mishf(float v) {
    float sp = (v > 20.f) ? v : log1pf(__expf(v));
    return v * tanhf(sp);
}

// ---------------------------------------------------------------------------
// Norm kernels
// ---------------------------------------------------------------------------
__global__ void dwn_kernel(const float* __restrict__ d_w) {
    int b = blockIdx.x / KW, k = blockIdx.x % KW;
    __shared__ float red[256];
    float s = 0.f;
    for (int c = threadIdx.x; c < CH; c += 256) {
        float v = d_w[((long)b * CH + c) * KW + k];
        s += v * v;
    }
    red[threadIdx.x] = s;
    __syncthreads();
    for (int off = 128; off > 0; off >>= 1) {
        if (threadIdx.x < off) red[threadIdx.x] += red[threadIdx.x + off];
        __syncthreads();
    }
    if (threadIdx.x == 0)
        g_dwn[b * KW + k] = 1.f / fmaxf(sqrtf(red[0]), 1e-12f);
}

__global__ void pwn_kernel(const float* __restrict__ p_w) {
    int b  = blockIdx.x / (OO / 32);
    int o0 = (blockIdx.x % (OO / 32)) * 32;
    int oi = threadIdx.x & 31, cg = threadIdx.x >> 5;
    int o = o0 + oi;
    float s = 0.f;
    for (int c = cg; c < CH; c += 8) {
        float v = p_w[((long)b * CH + c) * OO + o];
        s += v * v;
    }
    __shared__ float red[8][33];
    red[cg][oi] = s;
    __syncthreads();
    if (cg == 0) {
        float t = 0.f;
        #pragma unroll
        for (int j = 0; j < 8; j++) t += red[j][oi];
        g_pwn[b * OO + o] = 1.f / fmaxf(sqrtf(t), 1e-12f);
    }
}

// ---------------------------------------------------------------------------
// Fused: depthwise conv + transpose + fp16 quantize, packed output (hi only)
// ---------------------------------------------------------------------------
__global__ void __launch_bounds__(256)
convT_kernel(const float* __restrict__ d_w, const float* __restrict__ d_g,
             const float* __restrict__ d_b, const float* __restrict__ p_g,
             char* __restrict__ hi) {
    __shared__ float tile[32][41];
    int b = blockIdx.z, c0 = blockIdx.y * 32, t0 = blockIdx.x * 32;
    int tid = threadIdx.y * 32 + threadIdx.x;

    const float* hbase = g_h + ((size_t)b * CH + c0) * TT;
    #pragma unroll
    for (int i = tid; i < 32 * 40; i += 256) {
        int c = i / 40, j = i % 40;
        int t = t0 - 4 + j;
        tile[c][j] = (t >= 0 && t < TT) ? hbase[(size_t)c * TT + t] : 0.f;
    }
    __syncthreads();

    int tx = threadIdx.x;
    int c  = c0 + tx;
    float gg   = d_g[b * CH + c];
    float pg   = p_g[b * CH + c];
    float bias = d_b[b * CH + c];
    float w[KW];
    #pragma unroll
    for (int k = 0; k < KW; k++)
        w[k] = d_w[((size_t)b * CH + c) * KW + k] * g_dwn[b * KW + k] * gg;

    #pragma unroll
    for (int i = 0; i < 4; i++) {
        int tl = threadIdx.y + i * 8;
        float acc = bias;
        #pragma unroll
        for (int k = 0; k < KW; k++) acc = fmaf(tile[tx][tl + k], w[k], acc);
        float v = acc * pg;
        size_t off = (size_t)b * PB_1K + pk_off(t0 + tl, c, 32);
        *(__half*)(hi + off) = __float2half(v);
    }
}

// ---------------------------------------------------------------------------
// Elementwise fp16 hi/lo split to packed format. src: [batches][R][K] fp32.
// lo may be nullptr (A operands don't need it).
// ---------------------------------------------------------------------------
__global__ void splitp_kernel(const float* __restrict__ src,
                              char* __restrict__ hi, char* __restrict__ lo,
                              int R, int K, long pb_bytes, int n4total) {
    int i = blockIdx.x * blockDim.x + threadIdx.x;
    if (i >= n4total) return;
    long e = (long)i * 4;
    long perb = (long)R * K;
    int bb = (int)(e / perb);
    long rem = e - (long)bb * perb;
    int r = (int)(rem / K), k = (int)(rem % K);
    float4 v = ((const float4*)src)[i];
    __half h0 = __float2half(v.x), h1 = __float2half(v.y);
    __half h2 = __float2half(v.z), h3 = __float2half(v.w);
    __half2 hA, hB;
    hA.x = h0; hA.y = h1; hB.x = h2; hB.y = h3;
    size_t off = (size_t)bb * pb_bytes + pk_off(r, k, K >> 5);
    uint2 hw;
    hw.x = *(uint32_t*)&hA; hw.y = *(uint32_t*)&hB;
    *(uint2*)(hi + off) = hw;
    if (lo) {
        __half2 lA, lB;
        lA.x = __float2half(v.x - __half2float(h0));
        lA.y = __float2half(v.y - __half2float(h1));
        lB.x = __float2half(v.z - __half2float(h2));
        lB.y = __float2half(v.w - __half2float(h3));
        uint2 lw;
        lw.x = *(uint32_t*)&lA; lw.y = *(uint32_t*)&lB;
        *(uint2*)(lo + off) = lw;
    }
}

// ---------------------------------------------------------------------------
// Transpose + fp16 hi/lo split to packed: src[b][1024][1024]
// ---------------------------------------------------------------------------
__global__ void tcvtp_kernel(const float* __restrict__ src,
                             char* __restrict__ hi, char* __restrict__ lo) {
    __shared__ float tile[32][33];
    int b  = blockIdx.z;
    int c0 = blockIdx.x * 32;
    int r0 = blockIdx.y * 32;
    int tx = threadIdx.x, ty = threadIdx.y;
    const float* s = src + ((size_t)b * 1024 + r0) * 1024 + c0;
    #pragma unroll
    for (int i = 0; i < 32; i += 8)
        tile[ty + i][tx] = s[(size_t)(ty + i) * 1024 + tx];
    __syncthreads();
    #pragma unroll
    for (int i = 0; i < 32; i += 8) {
        float v = tile[tx][ty + i];
        __half h = __float2half(v);
        __half l = __float2half(v - __half2float(h));
        size_t off = (size_t)b * PB_1K + pk_off(c0 + ty + i, r0 + tx, 32);
        *(__half*)(hi + off) = h;
        *(__half*)(lo + off) = l;
    }
}

// ---------------------------------------------------------------------------
// PTX helpers
// ---------------------------------------------------------------------------
__device__ __forceinline__ uint32_t smem_u32(const void* p) {
    uint32_t a;
    asm("{ .reg .u64 t; cvta.to.shared.u64 t, %1; cvt.u32.u64 %0, t; }"
        : "=r"(a) : "l"(p));
    return a;
}

__device__ __forceinline__ void mbar_init(uint32_t m, uint32_t cnt) {
    asm volatile("mbarrier.init.shared.b64 [%0], %1;" :: "r"(m), "r"(cnt)
                 : "memory");
}

__device__ __forceinline__ void mbar_expect(uint32_t m, uint32_t tx) {
    asm volatile("mbarrier.arrive.expect_tx.shared.b64 _, [%0], %1;"
                 :: "r"(m), "r"(tx) : "memory");
}

__device__ __forceinline__ void bulk_g2s(uint32_t dst, const void* src,
                                         uint32_t bytes, uint32_t mbar) {
    asm volatile(
        "cp.async.bulk.shared::cluster.global.mbarrier::complete_tx::bytes "
        "[%0], [%1], %2, [%3];"
        :: "r"(dst), "l"(src), "r"(bytes), "r"(mbar) : "memory");
}

__device__ __forceinline__ void mbar_wait(uint32_t m, uint32_t parity) {
    uint32_t done = 0;
    while (!done)
        asm volatile(
            "{ .reg .pred P; mbarrier.try_wait.parity.shared.b64 P, [%1], %2; "
            "selp.b32 %0,1,0,P; }"
            : "=r"(done) : "r"(m), "r"(parity) : "memory");
}

__device__ __forceinline__ void ldsm4(uint32_t* r, uint32_t a) {
    asm volatile("ldmatrix.sync.aligned.m8n8.x4.shared.b16 {%0,%1,%2,%3}, [%4];"
                 : "=r"(r[0]), "=r"(r[1]), "=r"(r[2]), "=r"(r[3]) : "r"(a));
}

__device__ __forceinline__ void ldsm2(uint32_t* r, uint32_t a) {
    asm volatile("ldmatrix.sync.aligned.m8n8.x2.shared.b16 {%0,%1}, [%2];"
                 : "=r"(r[0]), "=r"(r[1]) : "r"(a));
}

__device__ __forceinline__ void mma16816(float* d, const uint32_t* a,
                                         const uint32_t* b) {
    asm volatile(
        "mma.sync.aligned.m16n8k16.row.col.f32.f16.f16.f32 "
        "{%0,%1,%2,%3}, {%4,%5,%6,%7}, {%8,%9}, {%0,%1,%2,%3};"
        : "+f"(d[0]), "+f"(d[1]), "+f"(d[2]), "+f"(d[3])
        : "r"(a[0]), "r"(a[1]), "r"(a[2]), "r"(a[3]), "r"(b[0]), "r"(b[1]));
}

// ---------------------------------------------------------------------------
// fp16 2-pass split GEMM: C[m][n] = sum_k A(m,k)*B(n,k)
//   A quantized to fp16 (hi only); B = Bh + Bl (~22-bit accurate).
//   Passes: Ah*Bh + Ah*Bl  (the dropped Al*B term is ~2^-11 relative).
// CTA 128x128, BK=32, 8 warps, warp tile 64x32, double buffer, 2 CTAs/SM.
// EPI 1: fp32 C = mish(v + e1[m])
// EPI 2: packed fp16 C = v*e1[b*OO+n] + e2[b*OO+n]   (hi only)
// EPI 3: fp32 C = v + e1[n] + e2[b][m][n]
// ---------------------------------------------------------------------------
#define SEG  SEGB                        // 10240 B per operand segment
#define STG  (3 * SEG)                   // Ah, Bh, Bl
#define SMEM_MMA (2 * STG + 16)          // + 2 mbarriers

template<int EPI>
__global__ void __launch_bounds__(256, 2)
mma_gemm(const char* __restrict__ Ah, long sA,
         const char* __restrict__ Bh, const char* __restrict__ Bl, long sB,
         void* __restrict__ C0, long sC,
         int M, int N, int K,
         const float* __restrict__ e1, const float* __restrict__ e2)
{
    extern __shared__ __align__(128) char sm[];
    const uint32_t smb = smem_u32(sm);
    const uint32_t mb0 = smb + 2 * STG;
    const int tid = threadIdx.x, lane = tid & 31, wid = tid >> 5;
    const int b = blockIdx.z;
    const int m0 = blockIdx.y * 128, n0 = blockIdx.x * 128;
    const int wm = wid >> 2, wn = wid & 3;
    const int nk = K >> 5;

    const char* pAh = Ah + (size_t)b * sA + (size_t)(m0 >> 7) * nk * SEGB;
    const char* pBh = Bh + (size_t)b * sB + (size_t)(n0 >> 7) * nk * SEGB;
    const char* pBl = Bl + (size_t)b * sB + (size_t)(n0 >> 7) * nk * SEGB;

    if (tid == 0) { mbar_init(mb0, 1); mbar_init(mb0 + 8, 1); }
    __syncthreads();

    float acc[4][4][4];
    #pragma unroll
    for (int i = 0; i < 4; i++)
        #pragma unroll
        for (int j = 0; j < 4; j++)
            #pragma unroll
            for (int r = 0; r < 4; r++) acc[i][j][r] = 0.f;

    auto issue = [&](int kc, int s) {
        if (tid == 0) {
            uint32_t mb = mb0 + s * 8;
            uint32_t sb = smb + s * STG;
            size_t go = (size_t)kc * SEGB;
            mbar_expect(mb, STG);
            bulk_g2s(sb + 0 * SEG, pAh + go, SEG, mb);
            bulk_g2s(sb + 1 * SEG, pBh + go, SEG, mb);
            bulk_g2s(sb + 2 * SEG, pBl + go, SEG, mb);
        }
    };

    auto compute = [&](int s) {
        const uint32_t sb = smb + s * STG;
        #pragma unroll
        for (int ks = 0; ks < 2; ks++) {
            uint32_t ah[4][4], bh[4][2], bl[4][2];
            #pragma unroll
            for (int i = 0; i < 4; i++) {
                uint32_t ad = sb +
                    (uint32_t)((wm * 64 + i * 16 + (lane & 15)) * PROWB) +
                    ks * 32 + (lane >> 4) * 16;
                ldsm4(ah[i], ad);
            }
            #pragma unroll
            for (int j = 0; j < 4; j++) {
                uint32_t bd = sb + SEG +
                    (uint32_t)((wn * 32 + j * 8 + (lane & 7)) * PROWB) +
                    ks * 32 + ((lane >> 3) & 1) * 16;
                ldsm2(bh[j], bd);
                ldsm2(bl[j], bd + SEG);
            }
            #pragma unroll
            for (int i = 0; i < 4; i++)
                #pragma unroll
                for (int j = 0; j < 4; j++) {
                    mma16816(acc[i][j], ah[i], bh[j]);
                    mma16816(acc[i][j], ah[i], bl[j]);
                }
        }
    };

    issue(0, 0);
    if (nk > 1) issue(1, 1);
    for (int kc = 0; kc < nk; kc++) {
        int s = kc & 1;
        mbar_wait(mb0 + s * 8, (kc >> 1) & 1);
        compute(s);
        __syncthreads();
        if (kc + 2 < nk) issue(kc + 2, s);
    }

    // --- epilogue ---
    const float* E1 = e1;
    const float* E2 = e2;
    if (EPI == 2) { E1 = e1 + b * OO; E2 = e2 + b * OO; }
    if (EPI == 3) { E2 = e2 + (size_t)b * M * N; }

    char* C0b = (char*)C0 + (size_t)b * sC;

    const int mrow0 = m0 + wm * 64;
    const int ncol0 = n0 + wn * 32;
    #pragma unroll
    for (int i = 0; i < 4; i++) {
        #pragma unroll
        for (int r = 0; r < 2; r++) {
            int m = mrow0 + i * 16 + (lane >> 2) + r * 8;
            #pragma unroll
            for (int j = 0; j < 4; j++) {
                int n = ncol0 + j * 8 + (lane & 3) * 2;
                float v0 = acc[i][j][r * 2 + 0];
                float v1 = acc[i][j][r * 2 + 1];
                size_t off = (size_t)m * N + n;
                if (EPI == 1) {
                    float bb = E1[m];
                    float2 o; o.x = mishf(v0 + bb); o.y = mishf(v1 + bb);
                    *(float2*)((float*)C0b + off) = o;
                } else if (EPI == 2) {
                    v0 = v0 * E1[n] + E2[n];
                    v1 = v1 * E1[n + 1] + E2[n + 1];
                    __half2 hv;
                    hv.x = __float2half(v0);
                    hv.y = __float2half(v1);
                    size_t po = pk_off(m, n, N >> 5);
                    *(uint32_t*)(C0b + po) = *(uint32_t*)&hv;
                } else {
                    float2 o;
                    o.x = v0 + E1[n]     + E2[off];
                    o.y = v1 + E1[n + 1] + E2[off + 1];
                    *(float2*)((float*)C0b + off) = o;
                }
            }
        }
    }
}

// ---------------------------------------------------------------------------
extern "C" void kernel_launch(void* const* d_in, const int* in_sizes, int n_in,
                              void* d_out, int out_size) {
    const float* x    = (const float*)d_in[0];
    const float* d_w  = (const float*)d_in[1];
    const float* d_g  = (const float*)d_in[2];
    const float* d_b  = (const float*)d_in[3];
    const float* p_w  = (const float*)d_in[4];
    const float* p_g  = (const float*)d_in[5];
    const float* p_b  = (const float*)d_in[6];
    const float* w1_w = (const float*)d_in[7];
    const float* w1_b = (const float*)d_in[8];
    const float* w2_w = (const float*)d_in[9];
    const float* w2_b = (const float*)d_in[10];
    float* out = (float*)d_out;

    void *p_gh, *p_gpwn;
    void *p_xh, *p_xl, *p_w1h, *p_w2h, *p_w2l;
    void *p_pth, *p_ptl, *p_yth, *p_y2h;
    cudaGetSymbolAddress(&p_gh,   g_h);
    cudaGetSymbolAddress(&p_gpwn, g_pwn);
    cudaGetSymbolAddress(&p_xh,   g_xph);
    cudaGetSymbolAddress(&p_xl,   g_xpl);
    cudaGetSymbolAddress(&p_w1h,  g_w1ph);
    cudaGetSymbolAddress(&p_w2h,  g_w2ph);
    cudaGetSymbolAddress(&p_w2l,  g_w2pl);
    cudaGetSymbolAddress(&p_pth,  g_pTph);
    cudaGetSymbolAddress(&p_ptl,  g_pTpl);
    cudaGetSymbolAddress(&p_yth,  g_yTph);
    cudaGetSymbolAddress(&p_y2h,  g_y2ph);
    float* gh   = (float*)p_gh;
    float* gpwn = (float*)p_gpwn;

    cudaFuncSetAttribute(mma_gemm<1>,
                         cudaFuncAttributeMaxDynamicSharedMemorySize, SMEM_MMA);
    cudaFuncSetAttribute(mma_gemm<2>,
                         cudaFuncAttributeMaxDynamicSharedMemorySize, SMEM_MMA);
    cudaFuncSetAttribute(mma_gemm<3>,
                         cudaFuncAttributeMaxDynamicSharedMemorySize, SMEM_MMA);

    // 1) norms + packed input conversions
    dwn_kernel<<<BB * KW, 256>>>(d_w);
    pwn_kernel<<<BB * (OO / 32), 256>>>(p_w);
    splitp_kernel<<<(BB * TT * DIN / 4 + 255) / 256, 256>>>(
        x, (char*)p_xh, (char*)p_xl, TT, DIN, PB_X, BB * TT * DIN / 4);
    splitp_kernel<<<(CH * DIN / 4 + 255) / 256, 256>>>(
        w1_w, (char*)p_w1h, nullptr, CH, DIN, 0L, CH * DIN / 4);
    splitp_kernel<<<(DIN * OO / 4 + 255) / 256, 256>>>(
        w2_w, (char*)p_w2h, (char*)p_w2l, DIN, OO, 0L, DIN * OO / 4);
    {
        dim3 grid(32, 32, BB);
        tcvtp_kernel<<<grid, dim3(32, 8)>>>(p_w, (char*)p_pth, (char*)p_ptl);
    }

    // 2) GEMM1: h = mish(w1 . x + w1_b)   M=CH, N=TT, K=DIN
    {
        dim3 grid(TT / 128, CH / 128, BB);
        mma_gemm<1><<<grid, 256, SMEM_MMA>>>(
            (char*)p_w1h, 0L,
            (char*)p_xh, (char*)p_xl, (long)PB_X,
            gh, (long)CH * TT * 4,
            CH, TT, DIN, w1_b, nullptr);
    }

    // 3) fused conv + transpose + fp16 quantize -> yT packed (hi only)
    {
        dim3 grid(TT / 32, CH / 32, BB);
        convT_kernel<<<grid, dim3(32, 8)>>>(d_w, d_g, d_b, p_g, (char*)p_yth);
    }

    // 4) GEMM2: y2 = (yT . pT)*pwn + p_b   M=TT, N=OO, K=CH  (packed fp16 out)
    {
        dim3 grid(OO / 128, TT / 128, BB);
        mma_gemm<2><<<grid, 256, SMEM_MMA>>>(
            (char*)p_yth, (long)PB_1K,
            (char*)p_pth, (char*)p_ptl, (long)PB_1K,
            p_y2h, (long)PB_1K,
            TT, OO, CH, gpwn, p_b);
    }

    // 5) GEMM3: out = y2 . w2^T + w2_b + x   M=TT, N=DIN, K=OO
    {
        dim3 grid(DIN / 128, TT / 128, BB);
        mma_gemm<3><<<grid, 256, SMEM_MMA>>>(
            (char*)p_y2h, (long)PB_1K,
            (char*)p_w2h, (char*)p_w2l, 0L,
            out, (long)TT * DIN * 4,
            TT, DIN, OO, w2_b, x);
    }
}

// round 9
// speedup vs baseline: 1.7391x; 1.3045x over previous
#include <cuda_runtime.h>
#include <cuda_fp16.h>
#include <math.h>
#include <stdint.h>

// Problem constants
#define BB   8
#define TT   1024
#define DIN  256
#define CH   1024   // D_H1
#define OO   1024   // D_H2
#define KW   9

// Packed-panel format for GEMM operands (fp16, 2 bytes):
//   operand [R][K] (K-major) -> tiles of 128 rows x 32 k,
//   byte offset = ((r>>7)*nks + (k>>5))*SEGB + (r&127)*PROWB + (k&31)*2
#define PROWB 80
#define SEGB  10240                     // 128 * 80
#define PB_X   (8 * 8 * SEGB)           // per-batch packed x   [1024][256]
#define PB_1K  (8 * 32 * SEGB)          // per-batch packed [1024][1024]
#define PB_W2  (2 * 32 * SEGB)          // packed w2 [256][1024]

__device__ __forceinline__ size_t pk_off(int r, int k, int nks) {
    return (size_t)((r >> 7) * nks + (k >> 5)) * SEGB +
           (size_t)(r & 127) * PROWB + (size_t)(k & 31) * 2;
}

// Scratch (device globals — no allocation allowed). Single-pass fp16:
// every operand exists as fp16 "hi" only.
__device__ float g_h [BB * CH * TT];     // mish(w1(x)), [b][c][t]
__device__ float g_pwn[BB * OO];
__device__ float g_dwn[BB * KW];
__device__ __align__(128) char g_xph [BB * PB_X];    // B of GEMM1
__device__ __align__(128) char g_w1ph[8 * 8 * SEGB]; // A of GEMM1
__device__ __align__(128) char g_w2ph[PB_W2];        // B of GEMM3
__device__ __align__(128) char g_pTph[BB * PB_1K];   // B of GEMM2
__device__ __align__(128) char g_yTph[BB * PB_1K];   // A of GEMM2
__device__ __align__(128) char g_y2ph[BB * PB_1K];   // A of GEMM3

__device__ __forceinline__ float mishf(float v) {
    float sp = (v > 20.f) ? v : log1pf(__expf(v));
    return v * tanhf(sp);
}

// ---------------------------------------------------------------------------
// Norm kernels
// ---------------------------------------------------------------------------
__global__ void dwn_kernel(const float* __restrict__ d_w) {
    int b = blockIdx.x / KW, k = blockIdx.x % KW;
    __shared__ float red[256];
    float s = 0.f;
    for (int c = threadIdx.x; c < CH; c += 256) {
        float v = d_w[((long)b * CH + c) * KW + k];
        s += v * v;
    }
    red[threadIdx.x] = s;
    __syncthreads();
    for (int off = 128; off > 0; off >>= 1) {
        if (threadIdx.x < off) red[threadIdx.x] += red[threadIdx.x + off];
        __syncthreads();
    }
    if (threadIdx.x == 0)
        g_dwn[b * KW + k] = 1.f / fmaxf(sqrtf(red[0]), 1e-12f);
}

__global__ void pwn_kernel(const float* __restrict__ p_w) {
    int b  = blockIdx.x / (OO / 32);
    int o0 = (blockIdx.x % (OO / 32)) * 32;
    int oi = threadIdx.x & 31, cg = threadIdx.x >> 5;
    int o = o0 + oi;
    float s = 0.f;
    for (int c = cg; c < CH; c += 8) {
        float v = p_w[((long)b * CH + c) * OO + o];
        s += v * v;
    }
    __shared__ float red[8][33];
    red[cg][oi] = s;
    __syncthreads();
    if (cg == 0) {
        float t = 0.f;
        #pragma unroll
        for (int j = 0; j < 8; j++) t += red[j][oi];
        g_pwn[b * OO + o] = 1.f / fmaxf(sqrtf(t), 1e-12f);
    }
}

// ---------------------------------------------------------------------------
// Fused: depthwise conv + transpose + fp16 quantize, packed output
// ---------------------------------------------------------------------------
__global__ void __launch_bounds__(256)
convT_kernel(const float* __restrict__ d_w, const float* __restrict__ d_g,
             const float* __restrict__ d_b, const float* __restrict__ p_g,
             char* __restrict__ hi) {
    __shared__ float tile[32][41];
    int b = blockIdx.z, c0 = blockIdx.y * 32, t0 = blockIdx.x * 32;
    int tid = threadIdx.y * 32 + threadIdx.x;

    const float* hbase = g_h + ((size_t)b * CH + c0) * TT;
    #pragma unroll
    for (int i = tid; i < 32 * 40; i += 256) {
        int c = i / 40, j = i % 40;
        int t = t0 - 4 + j;
        tile[c][j] = (t >= 0 && t < TT) ? hbase[(size_t)c * TT + t] : 0.f;
    }
    __syncthreads();

    int tx = threadIdx.x;
    int c  = c0 + tx;
    float gg   = d_g[b * CH + c];
    float pg   = p_g[b * CH + c];
    float bias = d_b[b * CH + c];
    float w[KW];
    #pragma unroll
    for (int k = 0; k < KW; k++)
        w[k] = d_w[((size_t)b * CH + c) * KW + k] * g_dwn[b * KW + k] * gg;

    #pragma unroll
    for (int i = 0; i < 4; i++) {
        int tl = threadIdx.y + i * 8;
        float acc = bias;
        #pragma unroll
        for (int k = 0; k < KW; k++) acc = fmaf(tile[tx][tl + k], w[k], acc);
        float v = acc * pg;
        size_t off = (size_t)b * PB_1K + pk_off(t0 + tl, c, 32);
        *(__half*)(hi + off) = __float2half(v);
    }
}

// ---------------------------------------------------------------------------
// Elementwise fp16 quantize to packed format. src: [batches][R][K] fp32.
// ---------------------------------------------------------------------------
__global__ void splitp_kernel(const float* __restrict__ src,
                              char* __restrict__ hi,
                              int R, int K, long pb_bytes, int n4total) {
    int i = blockIdx.x * blockDim.x + threadIdx.x;
    if (i >= n4total) return;
    long e = (long)i * 4;
    long perb = (long)R * K;
    int bb = (int)(e / perb);
    long rem = e - (long)bb * perb;
    int r = (int)(rem / K), k = (int)(rem % K);
    float4 v = ((const float4*)src)[i];
    __half2 hA, hB;
    hA.x = __float2half(v.x); hA.y = __float2half(v.y);
    hB.x = __float2half(v.z); hB.y = __float2half(v.w);
    size_t off = (size_t)bb * pb_bytes + pk_off(r, k, K >> 5);
    uint2 hw;
    hw.x = *(uint32_t*)&hA; hw.y = *(uint32_t*)&hB;
    *(uint2*)(hi + off) = hw;
}

// ---------------------------------------------------------------------------
// Transpose + fp16 quantize to packed: src[b][1024][1024]
// ---------------------------------------------------------------------------
__global__ void tcvtp_kernel(const float* __restrict__ src,
                             char* __restrict__ hi) {
    __shared__ float tile[32][33];
    int b  = blockIdx.z;
    int c0 = blockIdx.x * 32;
    int r0 = blockIdx.y * 32;
    int tx = threadIdx.x, ty = threadIdx.y;
    const float* s = src + ((size_t)b * 1024 + r0) * 1024 + c0;
    #pragma unroll
    for (int i = 0; i < 32; i += 8)
        tile[ty + i][tx] = s[(size_t)(ty + i) * 1024 + tx];
    __syncthreads();
    #pragma unroll
    for (int i = 0; i < 32; i += 8) {
        float v = tile[tx][ty + i];
        size_t off = (size_t)b * PB_1K + pk_off(c0 + ty + i, r0 + tx, 32);
        *(__half*)(hi + off) = __float2half(v);
    }
}

// ---------------------------------------------------------------------------
// PTX helpers
// ---------------------------------------------------------------------------
__device__ __forceinline__ uint32_t smem_u32(const void* p) {
    uint32_t a;
    asm("{ .reg .u64 t; cvta.to.shared.u64 t, %1; cvt.u32.u64 %0, t; }"
        : "=r"(a) : "l"(p));
    return a;
}

__device__ __forceinline__ void mbar_init(uint32_t m, uint32_t cnt) {
    asm volatile("mbarrier.init.shared.b64 [%0], %1;" :: "r"(m), "r"(cnt)
                 : "memory");
}

__device__ __forceinline__ void mbar_expect(uint32_t m, uint32_t tx) {
    asm volatile("mbarrier.arrive.expect_tx.shared.b64 _, [%0], %1;"
                 :: "r"(m), "r"(tx) : "memory");
}

__device__ __forceinline__ void bulk_g2s(uint32_t dst, const void* src,
                                         uint32_t bytes, uint32_t mbar) {
    asm volatile(
        "cp.async.bulk.shared::cluster.global.mbarrier::complete_tx::bytes "
        "[%0], [%1], %2, [%3];"
        :: "r"(dst), "l"(src), "r"(bytes), "r"(mbar) : "memory");
}

__device__ __forceinline__ void mbar_wait(uint32_t m, uint32_t parity) {
    uint32_t done = 0;
    while (!done)
        asm volatile(
            "{ .reg .pred P; mbarrier.try_wait.parity.shared.b64 P, [%1], %2; "
            "selp.b32 %0,1,0,P; }"
            : "=r"(done) : "r"(m), "r"(parity) : "memory");
}

__device__ __forceinline__ void ldsm4(uint32_t* r, uint32_t a) {
    asm volatile("ldmatrix.sync.aligned.m8n8.x4.shared.b16 {%0,%1,%2,%3}, [%4];"
                 : "=r"(r[0]), "=r"(r[1]), "=r"(r[2]), "=r"(r[3]) : "r"(a));
}

__device__ __forceinline__ void ldsm2(uint32_t* r, uint32_t a) {
    asm volatile("ldmatrix.sync.aligned.m8n8.x2.shared.b16 {%0,%1}, [%2];"
                 : "=r"(r[0]), "=r"(r[1]) : "r"(a));
}

__device__ __forceinline__ void mma16816(float* d, const uint32_t* a,
                                         const uint32_t* b) {
    asm volatile(
        "mma.sync.aligned.m16n8k16.row.col.f32.f16.f16.f32 "
        "{%0,%1,%2,%3}, {%4,%5,%6,%7}, {%8,%9}, {%0,%1,%2,%3};"
        : "+f"(d[0]), "+f"(d[1]), "+f"(d[2]), "+f"(d[3])
        : "r"(a[0]), "r"(a[1]), "r"(a[2]), "r"(a[3]), "r"(b[0]), "r"(b[1]));
}

// ---------------------------------------------------------------------------
// Single-pass fp16 GEMM: C[m][n] = sum_k A(m,k)*B(n,k), fp32 accumulate.
// CTA 128x128, BK=32, 8 warps, warp tile 64x32, 4-stage pipeline, 2 CTAs/SM.
// EPI 1: fp32 C = mish(v + e1[m])
// EPI 2: packed fp16 C = v*e1[b*OO+n] + e2[b*OO+n]
// EPI 3: fp32 C = v + e1[n] + e2[b][m][n]
// ---------------------------------------------------------------------------
#define SEG   SEGB                       // 10240 B per operand segment
#define STG   (2 * SEG)                  // Ah, Bh
#define NSTG  4
#define SMEM_MMA (NSTG * STG + NSTG * 8) // + mbarriers

template<int EPI>
__global__ void __launch_bounds__(256, 2)
mma_gemm(const char* __restrict__ Ah, long sA,
         const char* __restrict__ Bh, long sB,
         void* __restrict__ C0, long sC,
         int M, int N, int K,
         const float* __restrict__ e1, const float* __restrict__ e2)
{
    extern __shared__ __align__(128) char sm[];
    const uint32_t smb = smem_u32(sm);
    const uint32_t mb0 = smb + NSTG * STG;
    const int tid = threadIdx.x, lane = tid & 31, wid = tid >> 5;
    const int b = blockIdx.z;
    const int m0 = blockIdx.y * 128, n0 = blockIdx.x * 128;
    const int wm = wid >> 2, wn = wid & 3;
    const int nk = K >> 5;

    const char* pAh = Ah + (size_t)b * sA + (size_t)(m0 >> 7) * nk * SEGB;
    const char* pBh = Bh + (size_t)b * sB + (size_t)(n0 >> 7) * nk * SEGB;

    if (tid < NSTG) mbar_init(mb0 + tid * 8, 1);
    __syncthreads();

    float acc[4][4][4];
    #pragma unroll
    for (int i = 0; i < 4; i++)
        #pragma unroll
        for (int j = 0; j < 4; j++)
            #pragma unroll
            for (int r = 0; r < 4; r++) acc[i][j][r] = 0.f;

    auto issue = [&](int kc, int s) {
        if (tid == 0) {
            uint32_t mb = mb0 + s * 8;
            uint32_t sb = smb + s * STG;
            size_t go = (size_t)kc * SEGB;
            mbar_expect(mb, STG);
            bulk_g2s(sb,       pAh + go, SEG, mb);
            bulk_g2s(sb + SEG, pBh + go, SEG, mb);
        }
    };

    auto compute = [&](int s) {
        const uint32_t sb = smb + s * STG;
        #pragma unroll
        for (int ks = 0; ks < 2; ks++) {
            uint32_t ah[4][4], bh[4][2];
            #pragma unroll
            for (int i = 0; i < 4; i++) {
                uint32_t ad = sb +
                    (uint32_t)((wm * 64 + i * 16 + (lane & 15)) * PROWB) +
                    ks * 32 + (lane >> 4) * 16;
                ldsm4(ah[i], ad);
            }
            #pragma unroll
            for (int j = 0; j < 4; j++) {
                uint32_t bd = sb + SEG +
                    (uint32_t)((wn * 32 + j * 8 + (lane & 7)) * PROWB) +
                    ks * 32 + ((lane >> 3) & 1) * 16;
                ldsm2(bh[j], bd);
            }
            #pragma unroll
            for (int i = 0; i < 4; i++)
                #pragma unroll
                for (int j = 0; j < 4; j++)
                    mma16816(acc[i][j], ah[i], bh[j]);
        }
    };

    #pragma unroll
    for (int p = 0; p < NSTG - 1; p++)
        if (p < nk) issue(p, p);
    for (int kc = 0; kc < nk; kc++) {
        int s = kc & (NSTG - 1);
        mbar_wait(mb0 + s * 8, (kc / NSTG) & 1);
        compute(s);
        __syncthreads();
        if (kc + NSTG - 1 < nk)
            issue(kc + NSTG - 1, (kc + NSTG - 1) & (NSTG - 1));
    }

    // --- epilogue ---
    const float* E1 = e1;
    const float* E2 = e2;
    if (EPI == 2) { E1 = e1 + b * OO; E2 = e2 + b * OO; }
    if (EPI == 3) { E2 = e2 + (size_t)b * M * N; }

    char* C0b = (char*)C0 + (size_t)b * sC;

    const int mrow0 = m0 + wm * 64;
    const int ncol0 = n0 + wn * 32;
    #pragma unroll
    for (int i = 0; i < 4; i++) {
        #pragma unroll
        for (int r = 0; r < 2; r++) {
            int m = mrow0 + i * 16 + (lane >> 2) + r * 8;
            #pragma unroll
            for (int j = 0; j < 4; j++) {
                int n = ncol0 + j * 8 + (lane & 3) * 2;
                float v0 = acc[i][j][r * 2 + 0];
                float v1 = acc[i][j][r * 2 + 1];
                size_t off = (size_t)m * N + n;
                if (EPI == 1) {
                    float bb = E1[m];
                    float2 o; o.x = mishf(v0 + bb); o.y = mishf(v1 + bb);
                    *(float2*)((float*)C0b + off) = o;
                } else if (EPI == 2) {
                    v0 = v0 * E1[n] + E2[n];
                    v1 = v1 * E1[n + 1] + E2[n + 1];
                    __half2 hv;
                    hv.x = __float2half(v0);
                    hv.y = __float2half(v1);
                    size_t po = pk_off(m, n, N >> 5);
                    *(uint32_t*)(C0b + po) = *(uint32_t*)&hv;
                } else {
                    float2 o;
                    o.x = v0 + E1[n]     + E2[off];
                    o.y = v1 + E1[n + 1] + E2[off + 1];
                    *(float2*)((float*)C0b + off) = o;
                }
            }
        }
    }
}

// ---------------------------------------------------------------------------
extern "C" void kernel_launch(void* const* d_in, const int* in_sizes, int n_in,
                              void* d_out, int out_size) {
    const float* x    = (const float*)d_in[0];
    const float* d_w  = (const float*)d_in[1];
    const float* d_g  = (const float*)d_in[2];
    const float* d_b  = (const float*)d_in[3];
    const float* p_w  = (const float*)d_in[4];
    const float* p_g  = (const float*)d_in[5];
    const float* p_b  = (const float*)d_in[6];
    const float* w1_w = (const float*)d_in[7];
    const float* w1_b = (const float*)d_in[8];
    const float* w2_w = (const float*)d_in[9];
    const float* w2_b = (const float*)d_in[10];
    float* out = (float*)d_out;

    void *p_gh, *p_gpwn;
    void *p_xh, *p_w1h, *p_w2h, *p_pth, *p_yth, *p_y2h;
    cudaGetSymbolAddress(&p_gh,   g_h);
    cudaGetSymbolAddress(&p_gpwn, g_pwn);
    cudaGetSymbolAddress(&p_xh,   g_xph);
    cudaGetSymbolAddress(&p_w1h,  g_w1ph);
    cudaGetSymbolAddress(&p_w2h,  g_w2ph);
    cudaGetSymbolAddress(&p_pth,  g_pTph);
    cudaGetSymbolAddress(&p_yth,  g_yTph);
    cudaGetSymbolAddress(&p_y2h,  g_y2ph);
    float* gh   = (float*)p_gh;
    float* gpwn = (float*)p_gpwn;

    cudaFuncSetAttribute(mma_gemm<1>,
                         cudaFuncAttributeMaxDynamicSharedMemorySize, SMEM_MMA);
    cudaFuncSetAttribute(mma_gemm<2>,
                         cudaFuncAttributeMaxDynamicSharedMemorySize, SMEM_MMA);
    cudaFuncSetAttribute(mma_gemm<3>,
                         cudaFuncAttributeMaxDynamicSharedMemorySize, SMEM_MMA);

    // 1) norms + packed input conversions
    dwn_kernel<<<BB * KW, 256>>>(d_w);
    pwn_kernel<<<BB * (OO / 32), 256>>>(p_w);
    splitp_kernel<<<(BB * TT * DIN / 4 + 255) / 256, 256>>>(
        x, (char*)p_xh, TT, DIN, PB_X, BB * TT * DIN / 4);
    splitp_kernel<<<(CH * DIN / 4 + 255) / 256, 256>>>(
        w1_w, (char*)p_w1h, CH, DIN, 0L, CH * DIN / 4);
    splitp_kernel<<<(DIN * OO / 4 + 255) / 256, 256>>>(
        w2_w, (char*)p_w2h, DIN, OO, 0L, DIN * OO / 4);
    {
        dim3 grid(32, 32, BB);
        tcvtp_kernel<<<grid, dim3(32, 8)>>>(p_w, (char*)p_pth);
    }

    // 2) GEMM1: h = mish(w1 . x + w1_b)   M=CH, N=TT, K=DIN
    {
        dim3 grid(TT / 128, CH / 128, BB);
        mma_gemm<1><<<grid, 256, SMEM_MMA>>>(
            (char*)p_w1h, 0L,
            (char*)p_xh, (long)PB_X,
            gh, (long)CH * TT * 4,
            CH, TT, DIN, w1_b, nullptr);
    }

    // 3) fused conv + transpose + fp16 quantize -> yT packed
    {
        dim3 grid(TT / 32, CH / 32, BB);
        convT_kernel<<<grid, dim3(32, 8)>>>(d_w, d_g, d_b, p_g, (char*)p_yth);
    }

    // 4) GEMM2: y2 = (yT . pT)*pwn + p_b   M=TT, N=OO, K=CH  (packed fp16 out)
    {
        dim3 grid(OO / 128, TT / 128, BB);
        mma_gemm<2><<<grid, 256, SMEM_MMA>>>(
            (char*)p_yth, (long)PB_1K,
            (char*)p_pth, (long)PB_1K,
            p_y2h, (long)PB_1K,
            TT, OO, CH, gpwn, p_b);
    }

    // 5) GEMM3: out = y2 . w2^T + w2_b + x   M=TT, N=DIN, K=OO
    {
        dim3 grid(DIN / 128, TT / 128, BB);
        mma_gemm<3><<<grid, 256, SMEM_MMA>>>(
            (char*)p_y2h, (long)PB_1K,
            (char*)p_w2h, 0L,
            out, (long)TT * DIN * 4,
            TT, DIN, OO, w2_b, x);
    }
}

// round 10
// speedup vs baseline: 2.0741x; 1.1926x over previous
#include <cuda_runtime.h>
#include <cuda_fp16.h>
#include <math.h>
#include <stdint.h>

// Problem constants
#define BB   8
#define TT   1024
#define DIN  256
#define CH   1024   // D_H1
#define OO   1024   // D_H2
#define KW   9

// Packed-panel format for GEMM operands (fp16, 2 bytes):
//   operand [R][K] (K-major) -> tiles of 128 rows x 32 k,
//   byte offset = ((r>>7)*nks + (k>>5))*SEGB + (r&127)*PROWB + (k&31)*2
#define PROWB 80
#define SEGB  10240                     // 128 * 80
#define PB_X   (8 * 8 * SEGB)           // per-batch packed x   [1024][256]
#define PB_1K  (8 * 32 * SEGB)          // per-batch packed [1024][1024]
#define PB_W2  (2 * 32 * SEGB)          // packed w2 [256][1024]

__device__ __forceinline__ size_t pk_off(int r, int k, int nks) {
    return (size_t)((r >> 7) * nks + (k >> 5)) * SEGB +
           (size_t)(r & 127) * PROWB + (size_t)(k & 31) * 2;
}

// Scratch (device globals — no allocation allowed)
__device__ __half g_h [BB * CH * TT];    // mish(w1(x)), [b][c][t], fp16
__device__ float g_pwn[BB * OO];
__device__ float g_dwn[BB * KW];
__device__ __align__(128) char g_xph [BB * PB_X];    // B of GEMM1
__device__ __align__(128) char g_w1ph[8 * 8 * SEGB]; // A of GEMM1
__device__ __align__(128) char g_w2ph[PB_W2];        // B of GEMM3
__device__ __align__(128) char g_pTph[BB * PB_1K];   // B of GEMM2
__device__ __align__(128) char g_yTph[BB * PB_1K];   // A of GEMM2
__device__ __align__(128) char g_y2ph[BB * PB_1K];   // A of GEMM3

__device__ __forceinline__ float mishf(float v) {
    float sp = (v > 20.f) ? v : log1pf(__expf(v));
    return v * tanhf(sp);
}

// ---------------------------------------------------------------------------
// Fused preprocessing: one launch, grid-partitioned.
//   [0, 72)            dwn      : 1/||d_w[b,:,k]||
//   [72, 328)          pwn      : 1/||p_w[b,:,o]||
//   [328, 2376)        split x  -> g_xph
//   [2376, 2632)       split w1 -> g_w1ph
//   [2632, 2888)       split w2 -> g_w2ph
//   [2888, 11080)      transpose+quantize p_w -> g_pTph
// ---------------------------------------------------------------------------
#define NB_DWN 72
#define NB_PWN 256
#define NB_SX  2048
#define NB_SW1 256
#define NB_SW2 256
#define NB_TC  8192
#define NB_TOT (NB_DWN + NB_PWN + NB_SX + NB_SW1 + NB_SW2 + NB_TC)

__device__ __forceinline__ void split_part(const float* __restrict__ src,
                                           char* __restrict__ hi,
                                           int K, long pb_bytes,
                                           int blk, int tid) {
    int i = blk * 256 + tid;
    long e = (long)i * 4;
    long perb = (long)1024 * K;           // R is always 1024 or DIN here via K
    // generic: caller passes per-batch elems via perb param trick below
    (void)perb;
    // recomputed by caller wrappers
    (void)e;
    (void)src; (void)hi; (void)pb_bytes; (void)K;
}

__global__ void __launch_bounds__(256)
prep_kernel(const float* __restrict__ x,
            const float* __restrict__ d_w,
            const float* __restrict__ p_w,
            const float* __restrict__ w1_w,
            const float* __restrict__ w2_w,
            char* __restrict__ xph, char* __restrict__ w1ph,
            char* __restrict__ w2ph, char* __restrict__ pTph) {
    __shared__ float tile[32][33];
    const int blk = blockIdx.x, tid = threadIdx.x;

    if (blk < NB_DWN) {
        // --- dwn ---
        int b = blk / KW, k = blk % KW;
        float* red = &tile[0][0];
        float s = 0.f;
        for (int c = tid; c < CH; c += 256) {
            float v = d_w[((long)b * CH + c) * KW + k];
            s += v * v;
        }
        red[tid] = s;
        __syncthreads();
        for (int off = 128; off > 0; off >>= 1) {
            if (tid < off) red[tid] += red[tid + off];
            __syncthreads();
        }
        if (tid == 0)
            g_dwn[b * KW + k] = 1.f / fmaxf(sqrtf(red[0]), 1e-12f);
        return;
    }
    if (blk < NB_DWN + NB_PWN) {
        // --- pwn ---
        int idx = blk - NB_DWN;
        int b  = idx / (OO / 32);
        int o0 = (idx % (OO / 32)) * 32;
        int oi = tid & 31, cg = tid >> 5;
        int o = o0 + oi;
        float s = 0.f;
        for (int c = cg; c < CH; c += 8) {
            float v = p_w[((long)b * CH + c) * OO + o];
            s += v * v;
        }
        tile[cg][oi] = s;
        __syncthreads();
        if (cg == 0) {
            float t = 0.f;
            #pragma unroll
            for (int j = 0; j < 8; j++) t += tile[j][oi];
            g_pwn[b * OO + o] = 1.f / fmaxf(sqrtf(t), 1e-12f);
        }
        return;
    }
    if (blk < NB_DWN + NB_PWN + NB_SX + NB_SW1 + NB_SW2) {
        // --- elementwise fp16 quantize to packed ---
        const float* src;
        char* dst;
        int K, R;
        long pb;
        int i;
        if (blk < NB_DWN + NB_PWN + NB_SX) {
            i = (blk - NB_DWN - NB_PWN) * 256 + tid;
            src = x; dst = xph; K = DIN; R = TT; pb = PB_X;
        } else if (blk < NB_DWN + NB_PWN + NB_SX + NB_SW1) {
            i = (blk - NB_DWN - NB_PWN - NB_SX) * 256 + tid;
            src = w1_w; dst = w1ph; K = DIN; R = CH; pb = 0;
        } else {
            i = (blk - NB_DWN - NB_PWN - NB_SX - NB_SW1) * 256 + tid;
            src = w2_w; dst = w2ph; K = OO; R = DIN; pb = 0;
        }
        long e = (long)i * 4;
        long perb = (long)R * K;
        int bb = (int)(e / perb);
        long rem = e - (long)bb * perb;
        int r = (int)(rem / K), k = (int)(rem % K);
        float4 v = ((const float4*)src)[i];
        __half2 hA, hB;
        hA.x = __float2half(v.x); hA.y = __float2half(v.y);
        hB.x = __float2half(v.z); hB.y = __float2half(v.w);
        size_t off = (size_t)bb * pb + pk_off(r, k, K >> 5);
        uint2 hw;
        hw.x = *(uint32_t*)&hA; hw.y = *(uint32_t*)&hB;
        *(uint2*)(dst + off) = hw;
        return;
    }
    // --- transpose + quantize p_w -> pTph ---
    {
        int idx = blk - (NB_DWN + NB_PWN + NB_SX + NB_SW1 + NB_SW2);
        int b   = idx >> 10;
        int rem = idx & 1023;
        int c0  = (rem & 31) * 32;
        int r0  = (rem >> 5) * 32;
        int tx = tid & 31, ty = tid >> 5;
        const float* s = p_w + ((size_t)b * 1024 + r0) * 1024 + c0;
        #pragma unroll
        for (int i = 0; i < 32; i += 8)
            tile[ty + i][tx] = s[(size_t)(ty + i) * 1024 + tx];
        __syncthreads();
        #pragma unroll
        for (int i = 0; i < 32; i += 8) {
            float v = tile[tx][ty + i];
            size_t off = (size_t)b * PB_1K + pk_off(c0 + ty + i, r0 + tx, 32);
            *(__half*)(pTph + off) = __float2half(v);
        }
    }
}

// ---------------------------------------------------------------------------
// Fused: depthwise conv (fp16 input) + transpose + fp16 quantize, packed out
// ---------------------------------------------------------------------------
__global__ void __launch_bounds__(256)
convT_kernel(const float* __restrict__ d_w, const float* __restrict__ d_g,
             const float* __restrict__ d_b, const float* __restrict__ p_g,
             char* __restrict__ hi) {
    __shared__ float tile[32][41];
    int b = blockIdx.z, c0 = blockIdx.y * 32, t0 = blockIdx.x * 32;
    int tid = threadIdx.y * 32 + threadIdx.x;

    const __half* hbase = g_h + ((size_t)b * CH + c0) * TT;
    #pragma unroll
    for (int i = tid; i < 32 * 40; i += 256) {
        int c = i / 40, j = i % 40;
        int t = t0 - 4 + j;
        tile[c][j] = (t >= 0 && t < TT)
                     ? __half2float(hbase[(size_t)c * TT + t]) : 0.f;
    }
    __syncthreads();

    int tx = threadIdx.x;
    int c  = c0 + tx;
    float gg   = d_g[b * CH + c];
    float pg   = p_g[b * CH + c];
    float bias = d_b[b * CH + c];
    float w[KW];
    #pragma unroll
    for (int k = 0; k < KW; k++)
        w[k] = d_w[((size_t)b * CH + c) * KW + k] * g_dwn[b * KW + k] * gg;

    #pragma unroll
    for (int i = 0; i < 4; i++) {
        int tl = threadIdx.y + i * 8;
        float acc = bias;
        #pragma unroll
        for (int k = 0; k < KW; k++) acc = fmaf(tile[tx][tl + k], w[k], acc);
        float v = acc * pg;
        size_t off = (size_t)b * PB_1K + pk_off(t0 + tl, c, 32);
        *(__half*)(hi + off) = __float2half(v);
    }
}

// ---------------------------------------------------------------------------
// PTX helpers
// ---------------------------------------------------------------------------
__device__ __forceinline__ uint32_t smem_u32(const void* p) {
    uint32_t a;
    asm("{ .reg .u64 t; cvta.to.shared.u64 t, %1; cvt.u32.u64 %0, t; }"
        : "=r"(a) : "l"(p));
    return a;
}

__device__ __forceinline__ void mbar_init(uint32_t m, uint32_t cnt) {
    asm volatile("mbarrier.init.shared.b64 [%0], %1;" :: "r"(m), "r"(cnt)
                 : "memory");
}

__device__ __forceinline__ void mbar_expect(uint32_t m, uint32_t tx) {
    asm volatile("mbarrier.arrive.expect_tx.shared.b64 _, [%0], %1;"
                 :: "r"(m), "r"(tx) : "memory");
}

__device__ __forceinline__ void mbar_arrive(uint32_t m) {
    asm volatile("mbarrier.arrive.shared.b64 _, [%0];" :: "r"(m) : "memory");
}

__device__ __forceinline__ void bulk_g2s(uint32_t dst, const void* src,
                                         uint32_t bytes, uint32_t mbar) {
    asm volatile(
        "cp.async.bulk.shared::cluster.global.mbarrier::complete_tx::bytes "
        "[%0], [%1], %2, [%3];"
        :: "r"(dst), "l"(src), "r"(bytes), "r"(mbar) : "memory");
}

__device__ __forceinline__ void mbar_wait(uint32_t m, uint32_t parity) {
    uint32_t done = 0;
    while (!done)
        asm volatile(
            "{ .reg .pred P; mbarrier.try_wait.parity.shared.b64 P, [%1], %2; "
            "selp.b32 %0,1,0,P; }"
            : "=r"(done) : "r"(m), "r"(parity) : "memory");
}

__device__ __forceinline__ void ldsm4(uint32_t* r, uint32_t a) {
    asm volatile("ldmatrix.sync.aligned.m8n8.x4.shared.b16 {%0,%1,%2,%3}, [%4];"
                 : "=r"(r[0]), "=r"(r[1]), "=r"(r[2]), "=r"(r[3]) : "r"(a));
}

__device__ __forceinline__ void ldsm2(uint32_t* r, uint32_t a) {
    asm volatile("ldmatrix.sync.aligned.m8n8.x2.shared.b16 {%0,%1}, [%2];"
                 : "=r"(r[0]), "=r"(r[1]) : "r"(a));
}

__device__ __forceinline__ void mma16816(float* d, const uint32_t* a,
                                         const uint32_t* b) {
    asm volatile(
        "mma.sync.aligned.m16n8k16.row.col.f32.f16.f16.f32 "
        "{%0,%1,%2,%3}, {%4,%5,%6,%7}, {%8,%9}, {%0,%1,%2,%3};"
        : "+f"(d[0]), "+f"(d[1]), "+f"(d[2]), "+f"(d[3])
        : "r"(a[0]), "r"(a[1]), "r"(a[2]), "r"(a[3]), "r"(b[0]), "r"(b[1]));
}

// ---------------------------------------------------------------------------
// Single-pass fp16 GEMM, producer-consumer pipeline (no __syncthreads in loop)
// Per stage: full barrier (TMA tx) + empty barrier (count 8, per-warp arrive).
// Only the issuing thread (tid 0) waits on empty; warps free-run.
// CTA 128x128, BK=32, 8 warps, warp tile 64x32, 4 stages, 2 CTAs/SM.
// EPI 1: packed-row fp16 C = mish(v + e1[m])  (plain [M][N] half layout)
// EPI 2: packed fp16 C = v*e1[b*OO+n] + e2[b*OO+n]
// EPI 3: fp32 C = v + e1[n] + e2[b][m][n]
// ---------------------------------------------------------------------------
#define SEG   SEGB                       // 10240 B per operand segment
#define STG   (2 * SEG)                  // Ah, Bh
#define NSTG  4
#define SMEM_MMA (NSTG * STG + 2 * NSTG * 8)

template<int EPI>
__global__ void __launch_bounds__(256, 2)
mma_gemm(const char* __restrict__ Ah, long sA,
         const char* __restrict__ Bh, long sB,
         void* __restrict__ C0, long sC,
         int M, int N, int K,
         const float* __restrict__ e1, const float* __restrict__ e2)
{
    extern __shared__ __align__(128) char sm[];
    const uint32_t smb = smem_u32(sm);
    const uint32_t mbF = smb + NSTG * STG;          // full barriers
    const uint32_t mbE = mbF + NSTG * 8;            // empty barriers
    const int tid = threadIdx.x, lane = tid & 31, wid = tid >> 5;
    const int b = blockIdx.z;
    const int m0 = blockIdx.y * 128, n0 = blockIdx.x * 128;
    const int wm = wid >> 2, wn = wid & 3;
    const int nk = K >> 5;

    const char* pAh = Ah + (size_t)b * sA + (size_t)(m0 >> 7) * nk * SEGB;
    const char* pBh = Bh + (size_t)b * sB + (size_t)(n0 >> 7) * nk * SEGB;

    if (tid < NSTG) {
        mbar_init(mbF + tid * 8, 1);
        mbar_init(mbE + tid * 8, 8);
    }
    __syncthreads();

    float acc[4][4][4];
    #pragma unroll
    for (int i = 0; i < 4; i++)
        #pragma unroll
        for (int j = 0; j < 4; j++)
            #pragma unroll
            for (int r = 0; r < 4; r++) acc[i][j][r] = 0.f;

    auto issue = [&](int kc) {
        int s = kc & (NSTG - 1);
        uint32_t mb = mbF + s * 8;
        uint32_t sb = smb + s * STG;
        size_t go = (size_t)kc * SEGB;
        mbar_expect(mb, STG);
        bulk_g2s(sb,       pAh + go, SEG, mb);
        bulk_g2s(sb + SEG, pBh + go, SEG, mb);
    };

    auto compute = [&](int s) {
        const uint32_t sb = smb + s * STG;
        #pragma unroll
        for (int ks = 0; ks < 2; ks++) {
            uint32_t ah[4][4], bh[4][2];
            #pragma unroll
            for (int i = 0; i < 4; i++) {
                uint32_t ad = sb +
                    (uint32_t)((wm * 64 + i * 16 + (lane & 15)) * PROWB) +
                    ks * 32 + (lane >> 4) * 16;
                ldsm4(ah[i], ad);
            }
            #pragma unroll
            for (int j = 0; j < 4; j++) {
                uint32_t bd = sb + SEG +
                    (uint32_t)((wn * 32 + j * 8 + (lane & 7)) * PROWB) +
                    ks * 32 + ((lane >> 3) & 1) * 16;
                ldsm2(bh[j], bd);
            }
            #pragma unroll
            for (int i = 0; i < 4; i++)
                #pragma unroll
                for (int j = 0; j < 4; j++)
                    mma16816(acc[i][j], ah[i], bh[j]);
        }
    };

    if (tid == 0) {
        #pragma unroll
        for (int p = 0; p < NSTG - 1; p++)
            if (p < nk) issue(p);
    }
    for (int kc = 0; kc < nk; kc++) {
        int s = kc & (NSTG - 1);
        mbar_wait(mbF + s * 8, (kc >> 2) & 1);
        compute(s);
        if (lane == 0) mbar_arrive(mbE + s * 8);
        int kn = kc + NSTG - 1;
        if (kn < nk && tid == 0) {
            int sn = kn & (NSTG - 1);
            if (kn >= NSTG)
                mbar_wait(mbE + sn * 8, ((kn - NSTG) >> 2) & 1);
            issue(kn);
        }
    }

    // --- epilogue ---
    const float* E1 = e1;
    const float* E2 = e2;
    if (EPI == 2) { E1 = e1 + b * OO; E2 = e2 + b * OO; }
    if (EPI == 3) { E2 = e2 + (size_t)b * M * N; }

    char* C0b = (char*)C0 + (size_t)b * sC;

    const int mrow0 = m0 + wm * 64;
    const int ncol0 = n0 + wn * 32;
    #pragma unroll
    for (int i = 0; i < 4; i++) {
        #pragma unroll
        for (int r = 0; r < 2; r++) {
            int m = mrow0 + i * 16 + (lane >> 2) + r * 8;
            #pragma unroll
            for (int j = 0; j < 4; j++) {
                int n = ncol0 + j * 8 + (lane & 3) * 2;
                float v0 = acc[i][j][r * 2 + 0];
                float v1 = acc[i][j][r * 2 + 1];
                size_t off = (size_t)m * N + n;
                if (EPI == 1) {
                    float bb = E1[m];
                    __half2 hv;
                    hv.x = __float2half(mishf(v0 + bb));
                    hv.y = __float2half(mishf(v1 + bb));
                    *(__half2*)((__half*)C0b + off) = hv;
                } else if (EPI == 2) {
                    v0 = v0 * E1[n] + E2[n];
                    v1 = v1 * E1[n + 1] + E2[n + 1];
                    __half2 hv;
                    hv.x = __float2half(v0);
                    hv.y = __float2half(v1);
                    size_t po = pk_off(m, n, N >> 5);
                    *(uint32_t*)(C0b + po) = *(uint32_t*)&hv;
                } else {
                    float2 o;
                    o.x = v0 + E1[n]     + E2[off];
                    o.y = v1 + E1[n + 1] + E2[off + 1];
                    *(float2*)((float*)C0b + off) = o;
                }
            }
        }
    }
}

// ---------------------------------------------------------------------------
extern "C" void kernel_launch(void* const* d_in, const int* in_sizes, int n_in,
                              void* d_out, int out_size) {
    const float* x    = (const float*)d_in[0];
    const float* d_w  = (const float*)d_in[1];
    const float* d_g  = (const float*)d_in[2];
    const float* d_b  = (const float*)d_in[3];
    const float* p_w  = (const float*)d_in[4];
    const float* p_g  = (const float*)d_in[5];
    const float* p_b  = (const float*)d_in[6];
    const float* w1_w = (const float*)d_in[7];
    const float* w1_b = (const float*)d_in[8];
    const float* w2_w = (const float*)d_in[9];
    const float* w2_b = (const float*)d_in[10];
    float* out = (float*)d_out;

    void *p_gh, *p_gpwn;
    void *p_xh, *p_w1h, *p_w2h, *p_pth, *p_yth, *p_y2h;
    cudaGetSymbolAddress(&p_gh,   g_h);
    cudaGetSymbolAddress(&p_gpwn, g_pwn);
    cudaGetSymbolAddress(&p_xh,   g_xph);
    cudaGetSymbolAddress(&p_w1h,  g_w1ph);
    cudaGetSymbolAddress(&p_w2h,  g_w2ph);
    cudaGetSymbolAddress(&p_pth,  g_pTph);
    cudaGetSymbolAddress(&p_yth,  g_yTph);
    cudaGetSymbolAddress(&p_y2h,  g_y2ph);
    float* gpwn = (float*)p_gpwn;

    cudaFuncSetAttribute(mma_gemm<1>,
                         cudaFuncAttributeMaxDynamicSharedMemorySize, SMEM_MMA);
    cudaFuncSetAttribute(mma_gemm<2>,
                         cudaFuncAttributeMaxDynamicSharedMemorySize, SMEM_MMA);
    cudaFuncSetAttribute(mma_gemm<3>,
                         cudaFuncAttributeMaxDynamicSharedMemorySize, SMEM_MMA);

    // 1) fused preprocessing (norms + all input conversions), one launch
    prep_kernel<<<NB_TOT, 256>>>(x, d_w, p_w, w1_w, w2_w,
                                 (char*)p_xh, (char*)p_w1h,
                                 (char*)p_w2h, (char*)p_pth);

    // 2) GEMM1: h = mish(w1 . x + w1_b)   M=CH, N=TT, K=DIN  (fp16 out)
    {
        dim3 grid(TT / 128, CH / 128, BB);
        mma_gemm<1><<<grid, 256, SMEM_MMA>>>(
            (char*)p_w1h, 0L,
            (char*)p_xh, (long)PB_X,
            p_gh, (long)CH * TT * 2,
            CH, TT, DIN, w1_b, nullptr);
    }

    // 3) fused conv + transpose + fp16 quantize -> yT packed
    {
        dim3 grid(TT / 32, CH / 32, BB);
        convT_kernel<<<grid, dim3(32, 8)>>>(d_w, d_g, d_b, p_g, (char*)p_yth);
    }

    // 4) GEMM2: y2 = (yT . pT)*pwn + p_b   M=TT, N=OO, K=CH  (packed fp16 out)
    {
        dim3 grid(OO / 128, TT / 128, BB);
        mma_gemm<2><<<grid, 256, SMEM_MMA>>>(
            (char*)p_yth, (long)PB_1K,
            (char*)p_pth, (long)PB_1K,
            p_y2h, (long)PB_1K,
            TT, OO, CH, gpwn, p_b);
    }

    // 5) GEMM3: out = y2 . w2^T + w2_b + x   M=TT, N=DIN, K=OO
    {
        dim3 grid(DIN / 128, TT / 128, BB);
        mma_gemm<3><<<grid, 256, SMEM_MMA>>>(
            (char*)p_y2h, (long)PB_1K,
            (char*)p_w2h, 0L,
            out, (long)TT * DIN * 4,
            TT, DIN, OO, w2_b, x);
    }
}